// round 10
// baseline (speedup 1.0000x reference)
#include <cuda_runtime.h>
#include <cuda_bf16.h>
#include <cuda_fp16.h>
#include <cstdint>

#define NN 100000
#define EE 1600000
#define D  128
#define KTOT 384
#define NB  ((NN + 1023) / 1024)   // 98 scan blocks

typedef unsigned long long ull;

// ---------------- scratch (static device globals; no allocation) -------------
__device__ __align__(16) __half g_xh[(size_t)NN * D];   // fp16 image of x
__device__ __align__(16) __half g_f1[(size_t)NN * D];   // hop-1 (fp16)
__device__ __align__(16) __half g_f2[(size_t)NN * D];   // hop-2 (fp16)
__device__ int   g_deg[NN];
__device__ int   g_cursor[NN];
__device__ int   g_rowptr[NN + 1];
__device__ int   g_blocksum[NB];
__device__ int   g_blockoff[NB];
__device__ int2  g_dstval[EE];          // packed (dst, val-bits)
// Pre-swizzled fp16 image of W: 6 K-chunks of [128 n][64 k] fp16 (16 KB each)
__device__ __align__(16) unsigned char g_Wh[6 * 16384];

// ---------------- PTX helpers -------------------------------------------------
__device__ __forceinline__ uint32_t smem_u32(const void* p) {
    uint32_t a;
    asm("{ .reg .u64 t; cvta.to.shared.u64 t, %1; cvt.u32.u64 %0, t; }" : "=r"(a) : "l"(p));
    return a;
}

#define LDSM4(R, A)                                                         \
    asm volatile("ldmatrix.sync.aligned.m8n8.x4.shared.b16 "                \
                 "{%0,%1,%2,%3}, [%4];"                                     \
                 : "=r"((R)[0]), "=r"((R)[1]), "=r"((R)[2]), "=r"((R)[3])   \
                 : "r"(A))

#define MMAF16(DD, AA, B0, B1)                                              \
    asm volatile("mma.sync.aligned.m16n8k16.row.col.f32.f16.f16.f32 "       \
                 "{%0,%1,%2,%3},{%4,%5,%6,%7},{%8,%9},{%0,%1,%2,%3};"       \
                 : "+f"((DD)[0]), "+f"((DD)[1]), "+f"((DD)[2]), "+f"((DD)[3]) \
                 : "r"((AA)[0]), "r"((AA)[1]), "r"((AA)[2]), "r"((AA)[3]),  \
                   "r"(B0), "r"(B1))

__device__ __forceinline__ uint32_t swz(uint32_t bo) {
    return bo ^ ((bo >> 3) & 0x70);
}

__device__ __forceinline__ int warp_incl_scan(int val, int lane) {
    #pragma unroll
    for (int off = 1; off < 32; off <<= 1) {
        int t = __shfl_up_sync(0xffffffffu, val, off);
        if (lane >= off) val += t;
    }
    return val;
}

// ---------------- x -> fp16 image ---------------------------------------------
__global__ void xconv_kernel(const float4* __restrict__ x4) {
    int i = blockIdx.x * blockDim.x + threadIdx.x;      // over NN*D/8
    if (i >= NN * D / 8) return;
    float4 a = __ldg(&x4[i * 2]);
    float4 b = __ldg(&x4[i * 2 + 1]);
    __half2 h0 = __float22half2_rn(make_float2(a.x, a.y));
    __half2 h1 = __float22half2_rn(make_float2(a.z, a.w));
    __half2 h2 = __float22half2_rn(make_float2(b.x, b.y));
    __half2 h3 = __float22half2_rn(make_float2(b.z, b.w));
    uint4 o;
    o.x = *(uint32_t*)&h0; o.y = *(uint32_t*)&h1;
    o.z = *(uint32_t*)&h2; o.w = *(uint32_t*)&h3;
    ((uint4*)g_xh)[i] = o;
}

// ---------------- CSR build ---------------------------------------------------
__global__ void zero_deg_kernel() {
    int i = blockIdx.x * blockDim.x + threadIdx.x;
    if (i < NN) g_deg[i] = 0;
}

__global__ void hist_kernel(const int* __restrict__ src) {
    int t = blockIdx.x * blockDim.x + threadIdx.x;   // 4 edges per thread
    int e = t * 4;
    if (e + 3 < EE) {
        int4 s = __ldg((const int4*)(src + e));
        atomicAdd(&g_deg[s.x], 1);
        atomicAdd(&g_deg[s.y], 1);
        atomicAdd(&g_deg[s.z], 1);
        atomicAdd(&g_deg[s.w], 1);
    } else {
        for (int q = e; q < EE; q++) atomicAdd(&g_deg[__ldg(src + q)], 1);
    }
}

__global__ __launch_bounds__(1024)
void scan_local_kernel() {
    __shared__ int warpsums[32];
    int tid = threadIdx.x, lane = tid & 31, wid = tid >> 5;
    int i = blockIdx.x * 1024 + tid;
    int v = (i < NN) ? g_deg[i] : 0;
    int val = warp_incl_scan(v, lane);
    if (lane == 31) warpsums[wid] = val;
    __syncthreads();
    if (wid == 0) warpsums[lane] = warp_incl_scan(warpsums[lane], lane);
    __syncthreads();
    int excl = val - v + (wid > 0 ? warpsums[wid - 1] : 0);
    if (i < NN) g_rowptr[i] = excl;
    if (tid == 0) g_blocksum[blockIdx.x] = warpsums[31];
}

__global__ __launch_bounds__(128)
void scan_tops_kernel() {
    __shared__ int ws[4];
    int tid = threadIdx.x, lane = tid & 31, wid = tid >> 5;
    int v = (tid < NB) ? g_blocksum[tid] : 0;
    int val = warp_incl_scan(v, lane);
    if (lane == 31) ws[wid] = val;
    __syncthreads();
    if (tid == 0) {
        int a = ws[0];
        ws[0] = 0;
        #pragma unroll
        for (int q = 1; q < 4; q++) { int t = ws[q]; ws[q] = a; a += t; }
    }
    __syncthreads();
    if (tid < NB) g_blockoff[tid] = val - v + ws[wid];
}

__global__ void scan_add_kernel() {
    int i = blockIdx.x * blockDim.x + threadIdx.x;
    if (i < NN) {
        int r = g_rowptr[i] + g_blockoff[i >> 10];
        g_rowptr[i] = r;
        g_cursor[i] = r;
    }
    if (i == 0) g_rowptr[NN] = EE;
}

__global__ void scatter_kernel(const int* __restrict__ src,
                               const int* __restrict__ dst,
                               const float* __restrict__ val) {
    int t = blockIdx.x * blockDim.x + threadIdx.x;
    int e = t * 4;
    if (e + 3 < EE) {
        int4   s = __ldg((const int4*)(src + e));
        int4   d = __ldg((const int4*)(dst + e));
        float4 v = __ldg((const float4*)(val + e));
        int p0 = atomicAdd(&g_cursor[s.x], 1);
        int p1 = atomicAdd(&g_cursor[s.y], 1);
        int p2 = atomicAdd(&g_cursor[s.z], 1);
        int p3 = atomicAdd(&g_cursor[s.w], 1);
        g_dstval[p0] = make_int2(d.x, __float_as_int(v.x));
        g_dstval[p1] = make_int2(d.y, __float_as_int(v.y));
        g_dstval[p2] = make_int2(d.z, __float_as_int(v.z));
        g_dstval[p3] = make_int2(d.w, __float_as_int(v.w));
    } else {
        for (int q = e; q < EE; q++) {
            int dd = __ldg(dst + q);
            float vv = __ldg(val + q);
            int pos = atomicAdd(&g_cursor[__ldg(src + q)], 1);
            g_dstval[pos] = make_int2(dd, __float_as_int(vv));
        }
    }
}

// ---------------- SpMM (fp16 rows): warp/row, pipelined meta prefetch --------
__global__ __launch_bounds__(256)
void spmm_kernel(const uint2* __restrict__ fin, uint2* __restrict__ fout) {
    int warp = (blockIdx.x * blockDim.x + threadIdx.x) >> 5;
    int lane = threadIdx.x & 31;
    if (warp >= NN) return;
    int beg = __ldg(&g_rowptr[warp]);
    int end = __ldg(&g_rowptr[warp + 1]);

    float4 acc = make_float4(0.f, 0.f, 0.f, 0.f);
    int n8    = (end - beg) & ~7;
    int jend8 = beg + n8;

    if (n8 > 0) {
        int2 m[8];
        #pragma unroll
        for (int q = 0; q < 8; q++) m[q] = __ldg(&g_dstval[beg + q]);
        int j = beg;
        while (true) {
            uint2 a[8];
            #pragma unroll
            for (int q = 0; q < 8; q++)
                a[q] = __ldg(&fin[(size_t)m[q].x * 32 + lane]);
            int jn = j + 8;
            bool more = (jn < jend8);
            int2 mn[8];
            if (more) {
                #pragma unroll
                for (int q = 0; q < 8; q++) mn[q] = __ldg(&g_dstval[jn + q]);
            }
            #pragma unroll
            for (int q = 0; q < 8; q++) {
                float v = __int_as_float(m[q].y);
                float2 fa = __half22float2(*(__half2*)&a[q].x);
                float2 fb = __half22float2(*(__half2*)&a[q].y);
                acc.x = fmaf(v, fa.x, acc.x);
                acc.y = fmaf(v, fa.y, acc.y);
                acc.z = fmaf(v, fb.x, acc.z);
                acc.w = fmaf(v, fb.y, acc.w);
            }
            if (!more) break;
            #pragma unroll
            for (int q = 0; q < 8; q++) m[q] = mn[q];
            j = jn;
        }
    }
    for (int j = jend8; j < end; j++) {
        int2 m = __ldg(&g_dstval[j]);
        float v = __int_as_float(m.y);
        uint2 a = __ldg(&fin[(size_t)m.x * 32 + lane]);
        float2 fa = __half22float2(*(__half2*)&a.x);
        float2 fb = __half22float2(*(__half2*)&a.y);
        acc.x = fmaf(v, fa.x, acc.x);
        acc.y = fmaf(v, fa.y, acc.y);
        acc.z = fmaf(v, fb.x, acc.z);
        acc.w = fmaf(v, fb.y, acc.w);
    }
    __half2 o0 = __float22half2_rn(make_float2(acc.x, acc.y));
    __half2 o1 = __float22half2_rn(make_float2(acc.z, acc.w));
    uint2 o;
    o.x = *(uint32_t*)&o0; o.y = *(uint32_t*)&o1;
    fout[(size_t)warp * 32 + lane] = o;
}

// ---------------- W -> fp16, pre-swizzled SW128 chunks ------------------------
__global__ void wconv_kernel(const float* __restrict__ W) {
    int i = blockIdx.x * blockDim.x + threadIdx.x;   // over 128 * 384
    if (i >= 128 * KTOT) return;
    int n = i / KTOT, k = i % KTOT;
    __half h = __float2half_rn(W[i]);
    int c = k >> 6, kk = k & 63;
    uint32_t sw = swz((uint32_t)n * 128 + kk * 2);
    *(__half*)(g_Wh + c * 16384 + sw) = h;
}

// ---------------- mma.sync GEMM: out = [xh|f1|f2] @ Wh^T + b ------------------
#define SMEM_GEMM_BYTES (1024 + 2 * 16384)

__global__ __launch_bounds__(256, 2)
void gemm_mma_kernel(const float* __restrict__ bias,
                     float* __restrict__ out) {
    extern __shared__ unsigned char dsm[];
    const int tid  = threadIdx.x;
    const int lane = tid & 31;
    const int wid  = tid >> 5;
    const int warp_m = wid & 3;
    const int warp_n = wid >> 2;
    const int rbase  = blockIdx.x * 128;

    uint32_t sb0  = smem_u32(dsm);
    uint32_t base = (sb0 + 1023) & ~1023u;
    unsigned char* gp = dsm + (base - sb0);
    const uint32_t At = base, Bh = base + 16384;

    auto load_chunk = [&](int c) {
        const uint4* fsrc = (const uint4*)((c < 2) ? g_xh : (c < 4) ? g_f1 : g_f2);
        int koff = (c & 1) * 8;                       // uint4 (16B) offset in row
        #pragma unroll
        for (int it = 0; it < 4; it++) {
            int idx = tid + it * 256;                 // 1024 x 16B
            int row = idx >> 3, c8 = idx & 7;
            int grow = rbase + row;
            uint4 v = make_uint4(0u, 0u, 0u, 0u);
            if (grow < NN) v = fsrc[(size_t)grow * 16 + koff + c8];
            *(uint4*)(gp + swz((uint32_t)row * 128 + c8 * 16)) = v;
        }
        const uint4* wh = (const uint4*)(g_Wh + c * 16384);
        uint4* pBh = (uint4*)(gp + 16384);
        #pragma unroll
        for (int it = 0; it < 4; it++) {
            int i = tid + it * 256;
            pBh[i] = wh[i];
        }
    };

    float acc[2][8][4];
    #pragma unroll
    for (int mf = 0; mf < 2; mf++)
        #pragma unroll
        for (int nf = 0; nf < 8; nf++)
            #pragma unroll
            for (int q = 0; q < 4; q++) acc[mf][nf][q] = 0.f;

    const int g = lane >> 3, r = lane & 7;
    const int a_row_off = r + (g & 1) * 8;
    const int a_k_off   = (g >> 1) * 8;
    const int b_n_off   = r + (g >> 1) * 8;
    const int b_k_off   = (g & 1) * 8;

    load_chunk(0);
    __syncthreads();

    for (int c = 0; c < 6; c++) {
        #pragma unroll
        for (int ks = 0; ks < 4; ks++) {
            const int k0 = ks * 16;
            uint32_t ah[2][4];
            #pragma unroll
            for (int mf = 0; mf < 2; mf++) {
                uint32_t sw = swz((uint32_t)(warp_m * 32 + mf * 16 + a_row_off) * 128
                                  + (k0 + a_k_off) * 2);
                LDSM4(ah[mf], At + sw);
            }
            #pragma unroll
            for (int bq = 0; bq < 4; bq++) {
                uint32_t sw = swz((uint32_t)(warp_n * 64 + bq * 16 + b_n_off) * 128
                                  + (k0 + b_k_off) * 2);
                uint32_t bh[4];
                LDSM4(bh, Bh + sw);
                #pragma unroll
                for (int mf = 0; mf < 2; mf++) {
                    MMAF16(acc[mf][bq * 2 + 0], ah[mf], bh[0], bh[1]);
                    MMAF16(acc[mf][bq * 2 + 1], ah[mf], bh[2], bh[3]);
                }
            }
        }
        if (c < 5) {
            __syncthreads();
            load_chunk(c + 1);
            __syncthreads();
        }
    }

    // ---- epilogue: bias + store ----
    const int qrow = lane >> 2, qcol = (lane & 3) * 2;
    #pragma unroll
    for (int nf = 0; nf < 8; nf++) {
        int col = warp_n * 64 + nf * 8 + qcol;
        float b0 = __ldg(&bias[col]);
        float b1 = __ldg(&bias[col + 1]);
        #pragma unroll
        for (int mf = 0; mf < 2; mf++) {
            int row0 = rbase + warp_m * 32 + mf * 16 + qrow;
            if (row0 < NN)
                *(float2*)(out + (size_t)row0 * 128 + col) =
                    make_float2(acc[mf][nf][0] + b0, acc[mf][nf][1] + b1);
            int row1 = row0 + 8;
            if (row1 < NN)
                *(float2*)(out + (size_t)row1 * 128 + col) =
                    make_float2(acc[mf][nf][2] + b0, acc[mf][nf][3] + b1);
        }
    }
}

// ---------------- launch ------------------------------------------------------
extern "C" void kernel_launch(void* const* d_in, const int* in_sizes, int n_in,
                              void* d_out, int out_size) {
    const float* x        = (const float*)d_in[0];
    const int*   edge_src = (const int*)  d_in[1];
    const int*   edge_dst = (const int*)  d_in[2];
    const float* edge_val = (const float*)d_in[3];
    const float* W        = (const float*)d_in[4];
    const float* b        = (const float*)d_in[5];
    float* out = (float*)d_out;

    static bool init_done = false;
    static cudaStream_t s2;
    static cudaEvent_t ev_fork, ev_prep;
    if (!init_done) {
        cudaFuncSetAttribute(gemm_mma_kernel,
                             cudaFuncAttributeMaxDynamicSharedMemorySize,
                             SMEM_GEMM_BYTES);
        cudaStreamCreateWithFlags(&s2, cudaStreamNonBlocking);
        cudaEventCreateWithFlags(&ev_fork, cudaEventDisableTiming);
        cudaEventCreateWithFlags(&ev_prep, cudaEventDisableTiming);
        init_done = true;
    }

    uint2 *xhp, *f1p, *f2p;
    cudaGetSymbolAddress((void**)&xhp, g_xh);
    cudaGetSymbolAddress((void**)&f1p, g_f1);
    cudaGetSymbolAddress((void**)&f2p, g_f2);

    // Side stream: W + x fp16 images (L2-light, overlaps atomic-bound CSR build)
    cudaEventRecord(ev_fork, 0);
    cudaStreamWaitEvent(s2, ev_fork, 0);
    wconv_kernel<<<(128 * KTOT + 255) / 256, 256, 0, s2>>>(W);
    xconv_kernel<<<(NN * D / 8 + 255) / 256, 256, 0, s2>>>((const float4*)x);
    cudaEventRecord(ev_prep, s2);

    // Main: CSR build
    zero_deg_kernel<<<(NN + 255) / 256, 256>>>();
    hist_kernel<<<(EE / 4 + 255) / 256, 256>>>(edge_src);
    scan_local_kernel<<<NB, 1024>>>();
    scan_tops_kernel<<<1, 128>>>();
    scan_add_kernel<<<(NN + 255) / 256, 256>>>();
    scatter_kernel<<<(EE / 4 + 255) / 256, 256>>>(edge_src, edge_dst, edge_val);

    // Join: spmm1 needs g_xh
    cudaStreamWaitEvent(0, ev_prep, 0);

    // Two SpMM hops (fp16 gather, fp32 accumulate)
    int spmm_blocks = (NN + 7) / 8;
    spmm_kernel<<<spmm_blocks, 256>>>(xhp, f1p);
    spmm_kernel<<<spmm_blocks, 256>>>(f1p, f2p);

    // Tensor-core dense layer on [xh | f1 | f2]
    gemm_mma_kernel<<<(NN + 127) / 128, 256, SMEM_GEMM_BYTES>>>(b, out);
}

// round 11
// speedup vs baseline: 1.2153x; 1.2153x over previous
#include <cuda_runtime.h>
#include <cuda_bf16.h>
#include <cuda_fp16.h>
#include <cstdint>

#define NN 100000
#define EE 1600000
#define D  128
#define KTOT 384
#define NB  ((NN + 1023) / 1024)   // 98 scan blocks

typedef unsigned long long ull;

// ---------------- scratch (static device globals; no allocation) -------------
__device__ __align__(16) __half g_xh[(size_t)NN * D];   // fp16 image of x
__device__ __align__(16) __half g_f1[(size_t)NN * D];   // hop-1 (fp16)
__device__ __align__(16) __half g_f2[(size_t)NN * D];   // hop-2 (fp16)
__device__ int   g_deg[NN];
__device__ int   g_cursor[NN];
__device__ int   g_rowptr[NN + 1];
__device__ int   g_blocksum[NB];
__device__ int   g_blockoff[NB];
__device__ int2  g_dstval[EE];          // packed (dst, val-bits)
// Pre-swizzled fp16 image of W: 6 K-chunks of [128 n][64 k] fp16 (16 KB each)
__device__ __align__(16) unsigned char g_Wh[6 * 16384];

// ---------------- PTX helpers -------------------------------------------------
__device__ __forceinline__ uint32_t smem_u32(const void* p) {
    uint32_t a;
    asm("{ .reg .u64 t; cvta.to.shared.u64 t, %1; cvt.u32.u64 %0, t; }" : "=r"(a) : "l"(p));
    return a;
}

#define LDSM4(R, A)                                                         \
    asm volatile("ldmatrix.sync.aligned.m8n8.x4.shared.b16 "                \
                 "{%0,%1,%2,%3}, [%4];"                                     \
                 : "=r"((R)[0]), "=r"((R)[1]), "=r"((R)[2]), "=r"((R)[3])   \
                 : "r"(A))

#define MMAF16(DD, AA, B0, B1)                                              \
    asm volatile("mma.sync.aligned.m16n8k16.row.col.f32.f16.f16.f32 "       \
                 "{%0,%1,%2,%3},{%4,%5,%6,%7},{%8,%9},{%0,%1,%2,%3};"       \
                 : "+f"((DD)[0]), "+f"((DD)[1]), "+f"((DD)[2]), "+f"((DD)[3]) \
                 : "r"((AA)[0]), "r"((AA)[1]), "r"((AA)[2]), "r"((AA)[3]),  \
                   "r"(B0), "r"(B1))

__device__ __forceinline__ uint32_t swz(uint32_t bo) {
    return bo ^ ((bo >> 3) & 0x70);
}

__device__ __forceinline__ int warp_incl_scan(int val, int lane) {
    #pragma unroll
    for (int off = 1; off < 32; off <<= 1) {
        int t = __shfl_up_sync(0xffffffffu, val, off);
        if (lane >= off) val += t;
    }
    return val;
}

// ---------------- x -> fp16 image ---------------------------------------------
__global__ void xconv_kernel(const float4* __restrict__ x4) {
    int i = blockIdx.x * blockDim.x + threadIdx.x;      // over NN*D/8
    if (i >= NN * D / 8) return;
    float4 a = __ldg(&x4[i * 2]);
    float4 b = __ldg(&x4[i * 2 + 1]);
    __half2 h0 = __float22half2_rn(make_float2(a.x, a.y));
    __half2 h1 = __float22half2_rn(make_float2(a.z, a.w));
    __half2 h2 = __float22half2_rn(make_float2(b.x, b.y));
    __half2 h3 = __float22half2_rn(make_float2(b.z, b.w));
    uint4 o;
    o.x = *(uint32_t*)&h0; o.y = *(uint32_t*)&h1;
    o.z = *(uint32_t*)&h2; o.w = *(uint32_t*)&h3;
    ((uint4*)g_xh)[i] = o;
}

// ---------------- CSR build ---------------------------------------------------
__global__ void hist_kernel(const int* __restrict__ src) {
    int t = blockIdx.x * blockDim.x + threadIdx.x;   // 4 edges per thread
    int e = t * 4;
    if (e + 3 < EE) {
        int4 s = __ldg((const int4*)(src + e));
        atomicAdd(&g_deg[s.x], 1);
        atomicAdd(&g_deg[s.y], 1);
        atomicAdd(&g_deg[s.z], 1);
        atomicAdd(&g_deg[s.w], 1);
    } else {
        for (int q = e; q < EE; q++) atomicAdd(&g_deg[__ldg(src + q)], 1);
    }
}

__global__ __launch_bounds__(1024)
void scan_local_kernel() {
    __shared__ int warpsums[32];
    int tid = threadIdx.x, lane = tid & 31, wid = tid >> 5;
    int i = blockIdx.x * 1024 + tid;
    int v = (i < NN) ? g_deg[i] : 0;
    int val = warp_incl_scan(v, lane);
    if (lane == 31) warpsums[wid] = val;
    __syncthreads();
    if (wid == 0) warpsums[lane] = warp_incl_scan(warpsums[lane], lane);
    __syncthreads();
    int excl = val - v + (wid > 0 ? warpsums[wid - 1] : 0);
    if (i < NN) g_rowptr[i] = excl;
    if (tid == 0) g_blocksum[blockIdx.x] = warpsums[31];
}

__global__ __launch_bounds__(128)
void scan_tops_kernel() {
    __shared__ int ws[4];
    int tid = threadIdx.x, lane = tid & 31, wid = tid >> 5;
    int v = (tid < NB) ? g_blocksum[tid] : 0;
    int val = warp_incl_scan(v, lane);
    if (lane == 31) ws[wid] = val;
    __syncthreads();
    if (tid == 0) {
        int a = ws[0];
        ws[0] = 0;
        #pragma unroll
        for (int q = 1; q < 4; q++) { int t = ws[q]; ws[q] = a; a += t; }
    }
    __syncthreads();
    if (tid < NB) g_blockoff[tid] = val - v + ws[wid];
}

__global__ void scan_add_kernel() {
    int i = blockIdx.x * blockDim.x + threadIdx.x;
    if (i < NN) {
        int r = g_rowptr[i] + g_blockoff[i >> 10];
        g_rowptr[i] = r;
        g_cursor[i] = r;
    }
    if (i == 0) g_rowptr[NN] = EE;
}

__global__ void scatter_kernel(const int* __restrict__ src,
                               const int* __restrict__ dst,
                               const float* __restrict__ val) {
    int t = blockIdx.x * blockDim.x + threadIdx.x;
    int e = t * 4;
    if (e + 3 < EE) {
        int4   s = __ldg((const int4*)(src + e));
        int4   d = __ldg((const int4*)(dst + e));
        float4 v = __ldg((const float4*)(val + e));
        int p0 = atomicAdd(&g_cursor[s.x], 1);
        int p1 = atomicAdd(&g_cursor[s.y], 1);
        int p2 = atomicAdd(&g_cursor[s.z], 1);
        int p3 = atomicAdd(&g_cursor[s.w], 1);
        g_dstval[p0] = make_int2(d.x, __float_as_int(v.x));
        g_dstval[p1] = make_int2(d.y, __float_as_int(v.y));
        g_dstval[p2] = make_int2(d.z, __float_as_int(v.z));
        g_dstval[p3] = make_int2(d.w, __float_as_int(v.w));
    } else {
        for (int q = e; q < EE; q++) {
            int dd = __ldg(dst + q);
            float vv = __ldg(val + q);
            int pos = atomicAdd(&g_cursor[__ldg(src + q)], 1);
            g_dstval[pos] = make_int2(dd, __float_as_int(vv));
        }
    }
}

// ---------------- SpMM (fp16 rows): one warp per row, 8-deep unroll ----------
__global__ __launch_bounds__(256)
void spmm_kernel(const uint2* __restrict__ fin, uint2* __restrict__ fout) {
    int warp = (blockIdx.x * blockDim.x + threadIdx.x) >> 5;
    int lane = threadIdx.x & 31;
    if (warp >= NN) return;
    int beg = __ldg(&g_rowptr[warp]);
    int end = __ldg(&g_rowptr[warp + 1]);

    float4 acc = make_float4(0.f, 0.f, 0.f, 0.f);
    int j = beg;
    for (; j + 8 <= end; j += 8) {
        int2 m[8];
        uint2 a[8];
        #pragma unroll
        for (int q = 0; q < 8; q++) m[q] = __ldg(&g_dstval[j + q]);
        #pragma unroll
        for (int q = 0; q < 8; q++) a[q] = __ldg(&fin[(size_t)m[q].x * 32 + lane]);
        #pragma unroll
        for (int q = 0; q < 8; q++) {
            float v = __int_as_float(m[q].y);
            float2 fa = __half22float2(*(__half2*)&a[q].x);
            float2 fb = __half22float2(*(__half2*)&a[q].y);
            acc.x = fmaf(v, fa.x, acc.x);
            acc.y = fmaf(v, fa.y, acc.y);
            acc.z = fmaf(v, fb.x, acc.z);
            acc.w = fmaf(v, fb.y, acc.w);
        }
    }
    for (; j < end; j++) {
        int2 m = __ldg(&g_dstval[j]);
        float v = __int_as_float(m.y);
        uint2 a = __ldg(&fin[(size_t)m.x * 32 + lane]);
        float2 fa = __half22float2(*(__half2*)&a.x);
        float2 fb = __half22float2(*(__half2*)&a.y);
        acc.x = fmaf(v, fa.x, acc.x);
        acc.y = fmaf(v, fa.y, acc.y);
        acc.z = fmaf(v, fb.x, acc.z);
        acc.w = fmaf(v, fb.y, acc.w);
    }
    __half2 o0 = __float22half2_rn(make_float2(acc.x, acc.y));
    __half2 o1 = __float22half2_rn(make_float2(acc.z, acc.w));
    uint2 o;
    o.x = *(uint32_t*)&o0; o.y = *(uint32_t*)&o1;
    fout[(size_t)warp * 32 + lane] = o;
}

// ---------------- W -> fp16, pre-swizzled SW128 chunks ------------------------
__global__ void wconv_kernel(const float* __restrict__ W) {
    int i = blockIdx.x * blockDim.x + threadIdx.x;   // over 128 * 384
    if (i >= 128 * KTOT) return;
    int n = i / KTOT, k = i % KTOT;
    __half h = __float2half_rn(W[i]);
    int c = k >> 6, kk = k & 63;
    uint32_t sw = swz((uint32_t)n * 128 + kk * 2);
    *(__half*)(g_Wh + c * 16384 + sw) = h;
}

// ---------------- mma.sync GEMM: out = [xh|f1|f2] @ Wh^T + b ------------------
// CTA: 128 rows x 128 cols, K=384 in six 64-chunks. A fp16, W fp16 (1 product).
// 8 warps 4(m)x2(n), warp tile 32x64.
#define SMEM_GEMM_BYTES (1024 + 2 * 16384)

__global__ __launch_bounds__(256, 2)
void gemm_mma_kernel(const float* __restrict__ bias,
                     float* __restrict__ out) {
    extern __shared__ unsigned char dsm[];
    const int tid  = threadIdx.x;
    const int lane = tid & 31;
    const int wid  = tid >> 5;
    const int warp_m = wid & 3;
    const int warp_n = wid >> 2;
    const int rbase  = blockIdx.x * 128;

    uint32_t sb0  = smem_u32(dsm);
    uint32_t base = (sb0 + 1023) & ~1023u;
    unsigned char* gp = dsm + (base - sb0);
    const uint32_t At = base, Bh = base + 16384;

    auto load_chunk = [&](int c) {
        const uint4* fsrc = (const uint4*)((c < 2) ? g_xh : (c < 4) ? g_f1 : g_f2);
        int koff = (c & 1) * 8;                       // uint4 (16B) offset in row
        #pragma unroll
        for (int it = 0; it < 4; it++) {
            int idx = tid + it * 256;                 // 1024 x 16B
            int row = idx >> 3, c8 = idx & 7;
            int grow = rbase + row;
            uint4 v = make_uint4(0u, 0u, 0u, 0u);
            if (grow < NN) v = fsrc[(size_t)grow * 16 + koff + c8];
            *(uint4*)(gp + swz((uint32_t)row * 128 + c8 * 16)) = v;
        }
        const uint4* wh = (const uint4*)(g_Wh + c * 16384);
        uint4* pBh = (uint4*)(gp + 16384);
        #pragma unroll
        for (int it = 0; it < 4; it++) {
            int i = tid + it * 256;
            pBh[i] = wh[i];
        }
    };

    float acc[2][8][4];
    #pragma unroll
    for (int mf = 0; mf < 2; mf++)
        #pragma unroll
        for (int nf = 0; nf < 8; nf++)
            #pragma unroll
            for (int q = 0; q < 4; q++) acc[mf][nf][q] = 0.f;

    const int g = lane >> 3, r = lane & 7;
    const int a_row_off = r + (g & 1) * 8;
    const int a_k_off   = (g >> 1) * 8;
    const int b_n_off   = r + (g >> 1) * 8;
    const int b_k_off   = (g & 1) * 8;

    load_chunk(0);
    __syncthreads();

    for (int c = 0; c < 6; c++) {
        #pragma unroll
        for (int ks = 0; ks < 4; ks++) {
            const int k0 = ks * 16;
            uint32_t ah[2][4];
            #pragma unroll
            for (int mf = 0; mf < 2; mf++) {
                uint32_t sw = swz((uint32_t)(warp_m * 32 + mf * 16 + a_row_off) * 128
                                  + (k0 + a_k_off) * 2);
                LDSM4(ah[mf], At + sw);
            }
            #pragma unroll
            for (int bq = 0; bq < 4; bq++) {
                uint32_t sw = swz((uint32_t)(warp_n * 64 + bq * 16 + b_n_off) * 128
                                  + (k0 + b_k_off) * 2);
                uint32_t bh[4];
                LDSM4(bh, Bh + sw);
                #pragma unroll
                for (int mf = 0; mf < 2; mf++) {
                    MMAF16(acc[mf][bq * 2 + 0], ah[mf], bh[0], bh[1]);
                    MMAF16(acc[mf][bq * 2 + 1], ah[mf], bh[2], bh[3]);
                }
            }
        }
        if (c < 5) {
            __syncthreads();
            load_chunk(c + 1);
            __syncthreads();
        }
    }

    // ---- epilogue: bias + store ----
    const int qrow = lane >> 2, qcol = (lane & 3) * 2;
    #pragma unroll
    for (int nf = 0; nf < 8; nf++) {
        int col = warp_n * 64 + nf * 8 + qcol;
        float b0 = __ldg(&bias[col]);
        float b1 = __ldg(&bias[col + 1]);
        #pragma unroll
        for (int mf = 0; mf < 2; mf++) {
            int row0 = rbase + warp_m * 32 + mf * 16 + qrow;
            if (row0 < NN)
                *(float2*)(out + (size_t)row0 * 128 + col) =
                    make_float2(acc[mf][nf][0] + b0, acc[mf][nf][1] + b1);
            int row1 = row0 + 8;
            if (row1 < NN)
                *(float2*)(out + (size_t)row1 * 128 + col) =
                    make_float2(acc[mf][nf][2] + b0, acc[mf][nf][3] + b1);
        }
    }
}

// ---------------- launch ------------------------------------------------------
extern "C" void kernel_launch(void* const* d_in, const int* in_sizes, int n_in,
                              void* d_out, int out_size) {
    const float* x        = (const float*)d_in[0];
    const int*   edge_src = (const int*)  d_in[1];
    const int*   edge_dst = (const int*)  d_in[2];
    const float* edge_val = (const float*)d_in[3];
    const float* W        = (const float*)d_in[4];
    const float* b        = (const float*)d_in[5];
    float* out = (float*)d_out;

    static bool attr_set = false;
    static void* degp = nullptr;
    if (!attr_set) {
        cudaFuncSetAttribute(gemm_mma_kernel,
                             cudaFuncAttributeMaxDynamicSharedMemorySize,
                             SMEM_GEMM_BYTES);
        cudaGetSymbolAddress(&degp, g_deg);
        attr_set = true;
    }

    uint2 *xhp, *f1p, *f2p;
    cudaGetSymbolAddress((void**)&xhp, g_xh);
    cudaGetSymbolAddress((void**)&f1p, g_f1);
    cudaGetSymbolAddress((void**)&f2p, g_f2);

    // 1) Prep: W fp16 image, x fp16 image, CSR build (single stream — R10
    //    showed cross-stream capture costs more than any overlap saves)
    wconv_kernel<<<(128 * KTOT + 255) / 256, 256>>>(W);
    xconv_kernel<<<(NN * D / 8 + 255) / 256, 256>>>((const float4*)x);
    cudaMemsetAsync(degp, 0, NN * sizeof(int));
    hist_kernel<<<(EE / 4 + 255) / 256, 256>>>(edge_src);
    scan_local_kernel<<<NB, 1024>>>();
    scan_tops_kernel<<<1, 128>>>();
    scan_add_kernel<<<(NN + 255) / 256, 256>>>();
    scatter_kernel<<<(EE / 4 + 255) / 256, 256>>>(edge_src, edge_dst, edge_val);

    // 2) Two SpMM hops (fp16 gather, fp32 accumulate)
    int spmm_blocks = (NN + 7) / 8;
    spmm_kernel<<<spmm_blocks, 256>>>(xhp, f1p);
    spmm_kernel<<<spmm_blocks, 256>>>(f1p, f2p);

    // 3) Tensor-core dense layer on [xh | f1 | f2]
    gemm_mma_kernel<<<(NN + 127) / 128, 256, SMEM_GEMM_BYTES>>>(b, out);
}

// round 12
// speedup vs baseline: 1.2881x; 1.0598x over previous
#include <cuda_runtime.h>
#include <cuda_bf16.h>
#include <cuda_fp16.h>
#include <cstdint>

#define NN 100000
#define EE 1600000
#define D  128
#define KTOT 384
#define NB  ((NN + 1023) / 1024)            // 98 scan blocks
#define XBLOCKS ((NN * D / 8 + 255) / 256)  // 6250 xconv blocks
#define WBLOCKS ((128 * KTOT + 255) / 256)  // 192 wconv blocks

typedef unsigned long long ull;

// ---------------- scratch (static device globals; no allocation) -------------
__device__ __align__(16) __half g_xh[(size_t)NN * D];   // fp16 image of x
__device__ __align__(16) __half g_f1[(size_t)NN * D];   // hop-1 (fp16)
__device__ __align__(16) __half g_f2[(size_t)NN * D];   // hop-2 (fp16)
__device__ int   g_deg[NN];
__device__ int   g_cursor[NN];
__device__ int   g_rowptr[NN + 1];
__device__ int   g_blocksum[NB];
__device__ int2  g_dstval[EE];          // packed (dst, val-bits)
// Pre-swizzled fp16 image of W: 6 K-chunks of [128 n][64 k] fp16 (16 KB each)
__device__ __align__(16) unsigned char g_Wh[6 * 16384];

// ---------------- PTX helpers -------------------------------------------------
__device__ __forceinline__ uint32_t smem_u32(const void* p) {
    uint32_t a;
    asm("{ .reg .u64 t; cvta.to.shared.u64 t, %1; cvt.u32.u64 %0, t; }" : "=r"(a) : "l"(p));
    return a;
}

#define LDSM4(R, A)                                                         \
    asm volatile("ldmatrix.sync.aligned.m8n8.x4.shared.b16 "                \
                 "{%0,%1,%2,%3}, [%4];"                                     \
                 : "=r"((R)[0]), "=r"((R)[1]), "=r"((R)[2]), "=r"((R)[3])   \
                 : "r"(A))

#define MMAF16(DD, AA, B0, B1)                                              \
    asm volatile("mma.sync.aligned.m16n8k16.row.col.f32.f16.f16.f32 "       \
                 "{%0,%1,%2,%3},{%4,%5,%6,%7},{%8,%9},{%0,%1,%2,%3};"       \
                 : "+f"((DD)[0]), "+f"((DD)[1]), "+f"((DD)[2]), "+f"((DD)[3]) \
                 : "r"((AA)[0]), "r"((AA)[1]), "r"((AA)[2]), "r"((AA)[3]),  \
                   "r"(B0), "r"(B1))

#define CP_ASYNC16(dst, src, sz)                                            \
    asm volatile("cp.async.ca.shared.global [%0], [%1], 16, %2;"            \
                 :: "r"(dst), "l"(src), "r"(sz))
#define CP_COMMIT() asm volatile("cp.async.commit_group;" ::: "memory")
#define CP_WAIT(n)  asm volatile("cp.async.wait_group %0;" :: "n"(n) : "memory")

__device__ __forceinline__ uint32_t swz(uint32_t bo) {
    return bo ^ ((bo >> 3) & 0x70);
}

__device__ __forceinline__ int warp_incl_scan(int val, int lane) {
    #pragma unroll
    for (int off = 1; off < 32; off <<= 1) {
        int t = __shfl_up_sync(0xffffffffu, val, off);
        if (lane >= off) val += t;
    }
    return val;
}

// ---------------- fused prep: x -> fp16 image | W -> swizzled fp16 -----------
__global__ void prep_kernel(const float4* __restrict__ x4,
                            const float* __restrict__ W) {
    if (blockIdx.x < XBLOCKS) {
        int i = blockIdx.x * 256 + threadIdx.x;      // over NN*D/8
        if (i >= NN * D / 8) return;
        float4 a = __ldg(&x4[i * 2]);
        float4 b = __ldg(&x4[i * 2 + 1]);
        __half2 h0 = __float22half2_rn(make_float2(a.x, a.y));
        __half2 h1 = __float22half2_rn(make_float2(a.z, a.w));
        __half2 h2 = __float22half2_rn(make_float2(b.x, b.y));
        __half2 h3 = __float22half2_rn(make_float2(b.z, b.w));
        uint4 o;
        o.x = *(uint32_t*)&h0; o.y = *(uint32_t*)&h1;
        o.z = *(uint32_t*)&h2; o.w = *(uint32_t*)&h3;
        ((uint4*)g_xh)[i] = o;
    } else {
        int i = (blockIdx.x - XBLOCKS) * 256 + threadIdx.x;   // over 128*384
        if (i >= 128 * KTOT) return;
        int n = i / KTOT, k = i % KTOT;
        __half h = __float2half_rn(W[i]);
        int c = k >> 6, kk = k & 63;
        uint32_t sw = swz((uint32_t)n * 128 + kk * 2);
        *(__half*)(g_Wh + c * 16384 + sw) = h;
    }
}

// ---------------- CSR build ---------------------------------------------------
__global__ void hist_kernel(const int* __restrict__ src) {
    int t = blockIdx.x * blockDim.x + threadIdx.x;   // 4 edges per thread
    int e = t * 4;
    if (e + 3 < EE) {
        int4 s = __ldg((const int4*)(src + e));
        atomicAdd(&g_deg[s.x], 1);
        atomicAdd(&g_deg[s.y], 1);
        atomicAdd(&g_deg[s.z], 1);
        atomicAdd(&g_deg[s.w], 1);
    } else {
        for (int q = e; q < EE; q++) atomicAdd(&g_deg[__ldg(src + q)], 1);
    }
}

__global__ __launch_bounds__(1024)
void scan_local_kernel() {
    __shared__ int warpsums[32];
    int tid = threadIdx.x, lane = tid & 31, wid = tid >> 5;
    int i = blockIdx.x * 1024 + tid;
    int v = (i < NN) ? g_deg[i] : 0;
    int val = warp_incl_scan(v, lane);
    if (lane == 31) warpsums[wid] = val;
    __syncthreads();
    if (wid == 0) warpsums[lane] = warp_incl_scan(warpsums[lane], lane);
    __syncthreads();
    int excl = val - v + (wid > 0 ? warpsums[wid - 1] : 0);
    if (i < NN) g_rowptr[i] = excl;
    if (tid == 0) g_blocksum[blockIdx.x] = warpsums[31];
}

// Each block re-scans the 98 block sums in SMEM, then applies offsets.
__global__ __launch_bounds__(256)
void scan_add_kernel() {
    __shared__ int ws[4];
    __shared__ int boff[NB];
    int tid = threadIdx.x, lane = tid & 31, wid = tid >> 5;
    int v = 0, val = 0;
    if (tid < 128) {
        v = (tid < NB) ? g_blocksum[tid] : 0;
        val = warp_incl_scan(v, lane);
        if (lane == 31) ws[wid] = val;
    }
    __syncthreads();
    if (tid == 0) {
        int a = ws[0];
        ws[0] = 0;
        #pragma unroll
        for (int q = 1; q < 4; q++) { int t = ws[q]; ws[q] = a; a += t; }
    }
    __syncthreads();
    if (tid < NB) boff[tid] = val - v + ws[wid];
    __syncthreads();
    int i = blockIdx.x * 256 + tid;
    if (i < NN) {
        int r = g_rowptr[i] + boff[i >> 10];
        g_rowptr[i] = r;
        g_cursor[i] = r;
    }
    if (i == 0) g_rowptr[NN] = EE;
}

__global__ void scatter_kernel(const int* __restrict__ src,
                               const int* __restrict__ dst,
                               const float* __restrict__ val) {
    int t = blockIdx.x * blockDim.x + threadIdx.x;
    int e = t * 4;
    if (e + 3 < EE) {
        int4   s = __ldg((const int4*)(src + e));
        int4   d = __ldg((const int4*)(dst + e));
        float4 v = __ldg((const float4*)(val + e));
        int p0 = atomicAdd(&g_cursor[s.x], 1);
        int p1 = atomicAdd(&g_cursor[s.y], 1);
        int p2 = atomicAdd(&g_cursor[s.z], 1);
        int p3 = atomicAdd(&g_cursor[s.w], 1);
        g_dstval[p0] = make_int2(d.x, __float_as_int(v.x));
        g_dstval[p1] = make_int2(d.y, __float_as_int(v.y));
        g_dstval[p2] = make_int2(d.z, __float_as_int(v.z));
        g_dstval[p3] = make_int2(d.w, __float_as_int(v.w));
    } else {
        for (int q = e; q < EE; q++) {
            int dd = __ldg(dst + q);
            float vv = __ldg(val + q);
            int pos = atomicAdd(&g_cursor[__ldg(src + q)], 1);
            g_dstval[pos] = make_int2(dd, __float_as_int(vv));
        }
    }
}

// ---------------- SpMM (fp16 rows): one warp per row, 8-deep unroll ----------
__global__ __launch_bounds__(256)
void spmm_kernel(const uint2* __restrict__ fin, uint2* __restrict__ fout) {
    int warp = (blockIdx.x * blockDim.x + threadIdx.x) >> 5;
    int lane = threadIdx.x & 31;
    if (warp >= NN) return;
    int beg = __ldg(&g_rowptr[warp]);
    int end = __ldg(&g_rowptr[warp + 1]);

    float4 acc = make_float4(0.f, 0.f, 0.f, 0.f);
    int j = beg;
    for (; j + 8 <= end; j += 8) {
        int2 m[8];
        uint2 a[8];
        #pragma unroll
        for (int q = 0; q < 8; q++) m[q] = __ldg(&g_dstval[j + q]);
        #pragma unroll
        for (int q = 0; q < 8; q++) a[q] = __ldg(&fin[(size_t)m[q].x * 32 + lane]);
        #pragma unroll
        for (int q = 0; q < 8; q++) {
            float v = __int_as_float(m[q].y);
            float2 fa = __half22float2(*(__half2*)&a[q].x);
            float2 fb = __half22float2(*(__half2*)&a[q].y);
            acc.x = fmaf(v, fa.x, acc.x);
            acc.y = fmaf(v, fa.y, acc.y);
            acc.z = fmaf(v, fb.x, acc.z);
            acc.w = fmaf(v, fb.y, acc.w);
        }
    }
    for (; j < end; j++) {
        int2 m = __ldg(&g_dstval[j]);
        float v = __int_as_float(m.y);
        uint2 a = __ldg(&fin[(size_t)m.x * 32 + lane]);
        float2 fa = __half22float2(*(__half2*)&a.x);
        float2 fb = __half22float2(*(__half2*)&a.y);
        acc.x = fmaf(v, fa.x, acc.x);
        acc.y = fmaf(v, fa.y, acc.y);
        acc.z = fmaf(v, fb.x, acc.z);
        acc.w = fmaf(v, fb.y, acc.w);
    }
    __half2 o0 = __float22half2_rn(make_float2(acc.x, acc.y));
    __half2 o1 = __float22half2_rn(make_float2(acc.z, acc.w));
    uint2 o;
    o.x = *(uint32_t*)&o0; o.y = *(uint32_t*)&o1;
    fout[(size_t)warp * 32 + lane] = o;
}

// ---------------- mma.sync GEMM, cp.async double-buffered ---------------------
// CTA: 128x128, K=384 in six 64-chunks. Stage = 32KB (A 16K swizzled + B 16K).
#define STAGE_BYTES 32768
#define SMEM_GEMM_BYTES (1024 + 2 * STAGE_BYTES)

__global__ __launch_bounds__(256, 2)
void gemm_mma_kernel(const float* __restrict__ bias,
                     float* __restrict__ out) {
    extern __shared__ unsigned char dsm[];
    const int tid  = threadIdx.x;
    const int lane = tid & 31;
    const int wid  = tid >> 5;
    const int warp_m = wid & 3;
    const int warp_n = wid >> 2;
    const int rbase  = blockIdx.x * 128;

    uint32_t sb0  = smem_u32(dsm);
    uint32_t base = (sb0 + 1023) & ~1023u;

    auto issue_chunk = [&](int c, int buf) {
        const uint4* fsrc = (const uint4*)((c < 2) ? g_xh : (c < 4) ? g_f1 : g_f2);
        int koff = (c & 1) * 8;                       // uint4 (16B) offset in row
        uint32_t abase = base + buf * STAGE_BYTES;
        #pragma unroll
        for (int it = 0; it < 4; it++) {
            int idx = tid + it * 256;                 // 1024 x 16B
            int row = idx >> 3, c8 = idx & 7;
            int grow = rbase + row;
            const uint4* src = fsrc + ((grow < NN) ? ((size_t)grow * 16 + koff + c8) : 0);
            CP_ASYNC16(abase + swz((uint32_t)row * 128 + c8 * 16), src,
                       (grow < NN) ? 16 : 0);
        }
        const uint4* wh = (const uint4*)(g_Wh + c * 16384);
        uint32_t bbase = abase + 16384;
        #pragma unroll
        for (int it = 0; it < 4; it++) {
            int i = tid + it * 256;
            CP_ASYNC16(bbase + i * 16, wh + i, 16);
        }
    };

    float acc[2][8][4];
    #pragma unroll
    for (int mf = 0; mf < 2; mf++)
        #pragma unroll
        for (int nf = 0; nf < 8; nf++)
            #pragma unroll
            for (int q = 0; q < 4; q++) acc[mf][nf][q] = 0.f;

    const int g = lane >> 3, r = lane & 7;
    const int a_row_off = r + (g & 1) * 8;
    const int a_k_off   = (g >> 1) * 8;
    const int b_n_off   = r + (g >> 1) * 8;
    const int b_k_off   = (g & 1) * 8;

    issue_chunk(0, 0);
    CP_COMMIT();

    #pragma unroll
    for (int c = 0; c < 6; c++) {
        if (c < 5) {
            issue_chunk(c + 1, (c + 1) & 1);
            CP_COMMIT();
            CP_WAIT(1);
        } else {
            CP_WAIT(0);
        }
        __syncthreads();
        const uint32_t At = base + (c & 1) * STAGE_BYTES;
        const uint32_t Bh = At + 16384;
        #pragma unroll
        for (int ks = 0; ks < 4; ks++) {
            const int k0 = ks * 16;
            uint32_t ah[2][4];
            #pragma unroll
            for (int mf = 0; mf < 2; mf++) {
                uint32_t sw = swz((uint32_t)(warp_m * 32 + mf * 16 + a_row_off) * 128
                                  + (k0 + a_k_off) * 2);
                LDSM4(ah[mf], At + sw);
            }
            #pragma unroll
            for (int bq = 0; bq < 4; bq++) {
                uint32_t sw = swz((uint32_t)(warp_n * 64 + bq * 16 + b_n_off) * 128
                                  + (k0 + b_k_off) * 2);
                uint32_t bh[4];
                LDSM4(bh, Bh + sw);
                #pragma unroll
                for (int mf = 0; mf < 2; mf++) {
                    MMAF16(acc[mf][bq * 2 + 0], ah[mf], bh[0], bh[1]);
                    MMAF16(acc[mf][bq * 2 + 1], ah[mf], bh[2], bh[3]);
                }
            }
        }
        __syncthreads();
    }

    // ---- epilogue: bias + store ----
    const int qrow = lane >> 2, qcol = (lane & 3) * 2;
    #pragma unroll
    for (int nf = 0; nf < 8; nf++) {
        int col = warp_n * 64 + nf * 8 + qcol;
        float b0 = __ldg(&bias[col]);
        float b1 = __ldg(&bias[col + 1]);
        #pragma unroll
        for (int mf = 0; mf < 2; mf++) {
            int row0 = rbase + warp_m * 32 + mf * 16 + qrow;
            if (row0 < NN)
                *(float2*)(out + (size_t)row0 * 128 + col) =
                    make_float2(acc[mf][nf][0] + b0, acc[mf][nf][1] + b1);
            int row1 = row0 + 8;
            if (row1 < NN)
                *(float2*)(out + (size_t)row1 * 128 + col) =
                    make_float2(acc[mf][nf][2] + b0, acc[mf][nf][3] + b1);
        }
    }
}

// ---------------- launch ------------------------------------------------------
extern "C" void kernel_launch(void* const* d_in, const int* in_sizes, int n_in,
                              void* d_out, int out_size) {
    const float* x        = (const float*)d_in[0];
    const int*   edge_src = (const int*)  d_in[1];
    const int*   edge_dst = (const int*)  d_in[2];
    const float* edge_val = (const float*)d_in[3];
    const float* W        = (const float*)d_in[4];
    const float* b        = (const float*)d_in[5];
    float* out = (float*)d_out;

    static bool attr_set = false;
    static void* degp = nullptr;
    if (!attr_set) {
        cudaFuncSetAttribute(gemm_mma_kernel,
                             cudaFuncAttributeMaxDynamicSharedMemorySize,
                             SMEM_GEMM_BYTES);
        cudaGetSymbolAddress(&degp, g_deg);
        attr_set = true;
    }

    uint2 *xhp, *f1p, *f2p;
    cudaGetSymbolAddress((void**)&xhp, g_xh);
    cudaGetSymbolAddress((void**)&f1p, g_f1);
    cudaGetSymbolAddress((void**)&f2p, g_f2);

    // 1) Prep (fused x/W conversion) + CSR build, single stream
    prep_kernel<<<XBLOCKS + WBLOCKS, 256>>>((const float4*)x, W);
    cudaMemsetAsync(degp, 0, NN * sizeof(int));
    hist_kernel<<<(EE / 4 + 255) / 256, 256>>>(edge_src);
    scan_local_kernel<<<NB, 1024>>>();
    scan_add_kernel<<<(NN + 255) / 256, 256>>>();
    scatter_kernel<<<(EE / 4 + 255) / 256, 256>>>(edge_src, edge_dst, edge_val);

    // 2) Two SpMM hops (fp16 gather, fp32 accumulate)
    int spmm_blocks = (NN + 7) / 8;
    spmm_kernel<<<spmm_blocks, 256>>>(xhp, f1p);
    spmm_kernel<<<spmm_blocks, 256>>>(f1p, f2p);

    // 3) Tensor-core dense layer, cp.async double-buffered
    gemm_mma_kernel<<<(NN + 127) / 128, 256, SMEM_GEMM_BYTES>>>(b, out);
}

// round 13
// speedup vs baseline: 1.2917x; 1.0028x over previous
#include <cuda_runtime.h>
#include <cuda_bf16.h>
#include <cuda_fp16.h>
#include <cstdint>

#define NN 100000
#define EE 1600000
#define D  128
#define KTOT 384
#define NB  ((NN + 1023) / 1024)            // 98 scan blocks
#define XBLOCKS ((NN * D / 8 + 255) / 256)  // 6250 xconv blocks
#define WBLOCKS ((128 * KTOT + 255) / 256)  // 192 wconv blocks
#define HBLOCKS ((EE / 4 + 255) / 256)      // 1563 hist blocks

typedef unsigned long long ull;

// ---------------- scratch (static device globals; no allocation) -------------
__device__ __align__(16) __half g_xh[(size_t)NN * D];   // fp16 image of x
__device__ __align__(16) __half g_f1[(size_t)NN * D];   // hop-1 (fp16)
__device__ __align__(16) __half g_f2[(size_t)NN * D];   // hop-2 (fp16)
__device__ int   g_deg[NN];
__device__ int   g_cursor[NN];
__device__ int   g_rowptr[NN + 1];
__device__ int   g_blocksum[NB];
__device__ int2  g_dstval[EE];          // packed (dst, val-bits)
// Pre-swizzled fp16 image of W: 6 K-chunks of [128 n][64 k] fp16 (16 KB each)
__device__ __align__(16) unsigned char g_Wh[6 * 16384];

// ---------------- PTX helpers -------------------------------------------------
__device__ __forceinline__ uint32_t smem_u32(const void* p) {
    uint32_t a;
    asm("{ .reg .u64 t; cvta.to.shared.u64 t, %1; cvt.u32.u64 %0, t; }" : "=r"(a) : "l"(p));
    return a;
}

#define LDSM4(R, A)                                                         \
    asm volatile("ldmatrix.sync.aligned.m8n8.x4.shared.b16 "                \
                 "{%0,%1,%2,%3}, [%4];"                                     \
                 : "=r"((R)[0]), "=r"((R)[1]), "=r"((R)[2]), "=r"((R)[3])   \
                 : "r"(A))

#define MMAF16(DD, AA, B0, B1)                                              \
    asm volatile("mma.sync.aligned.m16n8k16.row.col.f32.f16.f16.f32 "       \
                 "{%0,%1,%2,%3},{%4,%5,%6,%7},{%8,%9},{%0,%1,%2,%3};"       \
                 : "+f"((DD)[0]), "+f"((DD)[1]), "+f"((DD)[2]), "+f"((DD)[3]) \
                 : "r"((AA)[0]), "r"((AA)[1]), "r"((AA)[2]), "r"((AA)[3]),  \
                   "r"(B0), "r"(B1))

#define CP_ASYNC16(dst, src, sz)                                            \
    asm volatile("cp.async.ca.shared.global [%0], [%1], 16, %2;"            \
                 :: "r"(dst), "l"(src), "r"(sz))
#define CP_COMMIT() asm volatile("cp.async.commit_group;" ::: "memory")
#define CP_WAIT(n)  asm volatile("cp.async.wait_group %0;" :: "n"(n) : "memory")

__device__ __forceinline__ uint32_t swz(uint32_t bo) {
    return bo ^ ((bo >> 3) & 0x70);
}

__device__ __forceinline__ int warp_incl_scan(int val, int lane) {
    #pragma unroll
    for (int off = 1; off < 32; off <<= 1) {
        int t = __shfl_up_sync(0xffffffffu, val, off);
        if (lane >= off) val += t;
    }
    return val;
}

// ------ fused prep: x->fp16 | W->swizzled fp16 | edge-src histogram ----------
// Independent jobs share one launch; block ranges select the job.
__global__ void prep_hist_kernel(const float4* __restrict__ x4,
                                 const float* __restrict__ W,
                                 const int* __restrict__ src) {
    if (blockIdx.x < XBLOCKS) {
        int i = blockIdx.x * 256 + threadIdx.x;      // over NN*D/8
        if (i >= NN * D / 8) return;
        float4 a = __ldg(&x4[i * 2]);
        float4 b = __ldg(&x4[i * 2 + 1]);
        __half2 h0 = __float22half2_rn(make_float2(a.x, a.y));
        __half2 h1 = __float22half2_rn(make_float2(a.z, a.w));
        __half2 h2 = __float22half2_rn(make_float2(b.x, b.y));
        __half2 h3 = __float22half2_rn(make_float2(b.z, b.w));
        uint4 o;
        o.x = *(uint32_t*)&h0; o.y = *(uint32_t*)&h1;
        o.z = *(uint32_t*)&h2; o.w = *(uint32_t*)&h3;
        ((uint4*)g_xh)[i] = o;
    } else if (blockIdx.x < XBLOCKS + WBLOCKS) {
        int i = (blockIdx.x - XBLOCKS) * 256 + threadIdx.x;   // over 128*384
        if (i >= 128 * KTOT) return;
        int n = i / KTOT, k = i % KTOT;
        __half h = __float2half_rn(W[i]);
        int c = k >> 6, kk = k & 63;
        uint32_t sw = swz((uint32_t)n * 128 + kk * 2);
        *(__half*)(g_Wh + c * 16384 + sw) = h;
    } else {
        int t = (blockIdx.x - XBLOCKS - WBLOCKS) * 256 + threadIdx.x;
        int e = t * 4;
        if (e + 3 < EE) {
            int4 s = __ldg((const int4*)(src + e));
            atomicAdd(&g_deg[s.x], 1);
            atomicAdd(&g_deg[s.y], 1);
            atomicAdd(&g_deg[s.z], 1);
            atomicAdd(&g_deg[s.w], 1);
        } else {
            for (int q = e; q < EE; q++) atomicAdd(&g_deg[__ldg(src + q)], 1);
        }
    }
}

// ---------------- CSR scan ----------------------------------------------------
__global__ __launch_bounds__(1024)
void scan_local_kernel() {
    __shared__ int warpsums[32];
    int tid = threadIdx.x, lane = tid & 31, wid = tid >> 5;
    int i = blockIdx.x * 1024 + tid;
    int v = (i < NN) ? g_deg[i] : 0;
    int val = warp_incl_scan(v, lane);
    if (lane == 31) warpsums[wid] = val;
    __syncthreads();
    if (wid == 0) warpsums[lane] = warp_incl_scan(warpsums[lane], lane);
    __syncthreads();
    int excl = val - v + (wid > 0 ? warpsums[wid - 1] : 0);
    if (i < NN) g_rowptr[i] = excl;
    if (tid == 0) g_blocksum[blockIdx.x] = warpsums[31];
}

// Each block re-scans the 98 block sums in SMEM, then applies offsets.
__global__ __launch_bounds__(256)
void scan_add_kernel() {
    __shared__ int ws[4];
    __shared__ int boff[NB];
    int tid = threadIdx.x, lane = tid & 31, wid = tid >> 5;
    int v = 0, val = 0;
    if (tid < 128) {
        v = (tid < NB) ? g_blocksum[tid] : 0;
        val = warp_incl_scan(v, lane);
        if (lane == 31) ws[wid] = val;
    }
    __syncthreads();
    if (tid == 0) {
        int a = ws[0];
        ws[0] = 0;
        #pragma unroll
        for (int q = 1; q < 4; q++) { int t = ws[q]; ws[q] = a; a += t; }
    }
    __syncthreads();
    if (tid < NB) boff[tid] = val - v + ws[wid];
    __syncthreads();
    int i = blockIdx.x * 256 + tid;
    if (i < NN) {
        int r = g_rowptr[i] + boff[i >> 10];
        g_rowptr[i] = r;
        g_cursor[i] = r;
    }
    if (i == 0) g_rowptr[NN] = EE;
}

__global__ void scatter_kernel(const int* __restrict__ src,
                               const int* __restrict__ dst,
                               const float* __restrict__ val) {
    int t = blockIdx.x * blockDim.x + threadIdx.x;
    int e = t * 4;
    if (e + 3 < EE) {
        int4   s = __ldg((const int4*)(src + e));
        int4   d = __ldg((const int4*)(dst + e));
        float4 v = __ldg((const float4*)(val + e));
        int p0 = atomicAdd(&g_cursor[s.x], 1);
        int p1 = atomicAdd(&g_cursor[s.y], 1);
        int p2 = atomicAdd(&g_cursor[s.z], 1);
        int p3 = atomicAdd(&g_cursor[s.w], 1);
        g_dstval[p0] = make_int2(d.x, __float_as_int(v.x));
        g_dstval[p1] = make_int2(d.y, __float_as_int(v.y));
        g_dstval[p2] = make_int2(d.z, __float_as_int(v.z));
        g_dstval[p3] = make_int2(d.w, __float_as_int(v.w));
    } else {
        for (int q = e; q < EE; q++) {
            int dd = __ldg(dst + q);
            float vv = __ldg(val + q);
            int pos = atomicAdd(&g_cursor[__ldg(src + q)], 1);
            g_dstval[pos] = make_int2(dd, __float_as_int(vv));
        }
    }
}

// -------- SpMM (fp16 rows): warp/row, 8-deep unroll + 4-wide tail tier -------
__global__ __launch_bounds__(256)
void spmm_kernel(const uint2* __restrict__ fin, uint2* __restrict__ fout) {
    int warp = (blockIdx.x * blockDim.x + threadIdx.x) >> 5;
    int lane = threadIdx.x & 31;
    if (warp >= NN) return;
    int beg = __ldg(&g_rowptr[warp]);
    int end = __ldg(&g_rowptr[warp + 1]);

    float4 acc = make_float4(0.f, 0.f, 0.f, 0.f);
    int j = beg;
    for (; j + 8 <= end; j += 8) {
        int2 m[8];
        uint2 a[8];
        #pragma unroll
        for (int q = 0; q < 8; q++) m[q] = __ldg(&g_dstval[j + q]);
        #pragma unroll
        for (int q = 0; q < 8; q++) a[q] = __ldg(&fin[(size_t)m[q].x * 32 + lane]);
        #pragma unroll
        for (int q = 0; q < 8; q++) {
            float v = __int_as_float(m[q].y);
            float2 fa = __half22float2(*(__half2*)&a[q].x);
            float2 fb = __half22float2(*(__half2*)&a[q].y);
            acc.x = fmaf(v, fa.x, acc.x);
            acc.y = fmaf(v, fa.y, acc.y);
            acc.z = fmaf(v, fb.x, acc.z);
            acc.w = fmaf(v, fb.y, acc.w);
        }
    }
    if (j + 4 <= end) {
        int2 m[4];
        uint2 a[4];
        #pragma unroll
        for (int q = 0; q < 4; q++) m[q] = __ldg(&g_dstval[j + q]);
        #pragma unroll
        for (int q = 0; q < 4; q++) a[q] = __ldg(&fin[(size_t)m[q].x * 32 + lane]);
        #pragma unroll
        for (int q = 0; q < 4; q++) {
            float v = __int_as_float(m[q].y);
            float2 fa = __half22float2(*(__half2*)&a[q].x);
            float2 fb = __half22float2(*(__half2*)&a[q].y);
            acc.x = fmaf(v, fa.x, acc.x);
            acc.y = fmaf(v, fa.y, acc.y);
            acc.z = fmaf(v, fb.x, acc.z);
            acc.w = fmaf(v, fb.y, acc.w);
        }
        j += 4;
    }
    for (; j < end; j++) {
        int2 m = __ldg(&g_dstval[j]);
        float v = __int_as_float(m.y);
        uint2 a = __ldg(&fin[(size_t)m.x * 32 + lane]);
        float2 fa = __half22float2(*(__half2*)&a.x);
        float2 fb = __half22float2(*(__half2*)&a.y);
        acc.x = fmaf(v, fa.x, acc.x);
        acc.y = fmaf(v, fa.y, acc.y);
        acc.z = fmaf(v, fb.x, acc.z);
        acc.w = fmaf(v, fb.y, acc.w);
    }
    __half2 o0 = __float22half2_rn(make_float2(acc.x, acc.y));
    __half2 o1 = __float22half2_rn(make_float2(acc.z, acc.w));
    uint2 o;
    o.x = *(uint32_t*)&o0; o.y = *(uint32_t*)&o1;
    fout[(size_t)warp * 32 + lane] = o;
}

// ---------------- mma.sync GEMM, cp.async double-buffered ---------------------
#define STAGE_BYTES 32768
#define SMEM_GEMM_BYTES (1024 + 2 * STAGE_BYTES)

__global__ __launch_bounds__(256, 2)
void gemm_mma_kernel(const float* __restrict__ bias,
                     float* __restrict__ out) {
    extern __shared__ unsigned char dsm[];
    const int tid  = threadIdx.x;
    const int lane = tid & 31;
    const int wid  = tid >> 5;
    const int warp_m = wid & 3;
    const int warp_n = wid >> 2;
    const int rbase  = blockIdx.x * 128;

    uint32_t sb0  = smem_u32(dsm);
    uint32_t base = (sb0 + 1023) & ~1023u;

    auto issue_chunk = [&](int c, int buf) {
        const uint4* fsrc = (const uint4*)((c < 2) ? g_xh : (c < 4) ? g_f1 : g_f2);
        int koff = (c & 1) * 8;                       // uint4 (16B) offset in row
        uint32_t abase = base + buf * STAGE_BYTES;
        #pragma unroll
        for (int it = 0; it < 4; it++) {
            int idx = tid + it * 256;                 // 1024 x 16B
            int row = idx >> 3, c8 = idx & 7;
            int grow = rbase + row;
            const uint4* src = fsrc + ((grow < NN) ? ((size_t)grow * 16 + koff + c8) : 0);
            CP_ASYNC16(abase + swz((uint32_t)row * 128 + c8 * 16), src,
                       (grow < NN) ? 16 : 0);
        }
        const uint4* wh = (const uint4*)(g_Wh + c * 16384);
        uint32_t bbase = abase + 16384;
        #pragma unroll
        for (int it = 0; it < 4; it++) {
            int i = tid + it * 256;
            CP_ASYNC16(bbase + i * 16, wh + i, 16);
        }
    };

    float acc[2][8][4];
    #pragma unroll
    for (int mf = 0; mf < 2; mf++)
        #pragma unroll
        for (int nf = 0; nf < 8; nf++)
            #pragma unroll
            for (int q = 0; q < 4; q++) acc[mf][nf][q] = 0.f;

    const int g = lane >> 3, r = lane & 7;
    const int a_row_off = r + (g & 1) * 8;
    const int a_k_off   = (g >> 1) * 8;
    const int b_n_off   = r + (g >> 1) * 8;
    const int b_k_off   = (g & 1) * 8;

    issue_chunk(0, 0);
    CP_COMMIT();

    #pragma unroll
    for (int c = 0; c < 6; c++) {
        if (c < 5) {
            issue_chunk(c + 1, (c + 1) & 1);
            CP_COMMIT();
            CP_WAIT(1);
        } else {
            CP_WAIT(0);
        }
        __syncthreads();
        const uint32_t At = base + (c & 1) * STAGE_BYTES;
        const uint32_t Bh = At + 16384;
        #pragma unroll
        for (int ks = 0; ks < 4; ks++) {
            const int k0 = ks * 16;
            uint32_t ah[2][4];
            #pragma unroll
            for (int mf = 0; mf < 2; mf++) {
                uint32_t sw = swz((uint32_t)(warp_m * 32 + mf * 16 + a_row_off) * 128
                                  + (k0 + a_k_off) * 2);
                LDSM4(ah[mf], At + sw);
            }
            #pragma unroll
            for (int bq = 0; bq < 4; bq++) {
                uint32_t sw = swz((uint32_t)(warp_n * 64 + bq * 16 + b_n_off) * 128
                                  + (k0 + b_k_off) * 2);
                uint32_t bh[4];
                LDSM4(bh, Bh + sw);
                #pragma unroll
                for (int mf = 0; mf < 2; mf++) {
                    MMAF16(acc[mf][bq * 2 + 0], ah[mf], bh[0], bh[1]);
                    MMAF16(acc[mf][bq * 2 + 1], ah[mf], bh[2], bh[3]);
                }
            }
        }
        __syncthreads();
    }

    // ---- epilogue: bias + store ----
    const int qrow = lane >> 2, qcol = (lane & 3) * 2;
    #pragma unroll
    for (int nf = 0; nf < 8; nf++) {
        int col = warp_n * 64 + nf * 8 + qcol;
        float b0 = __ldg(&bias[col]);
        float b1 = __ldg(&bias[col + 1]);
        #pragma unroll
        for (int mf = 0; mf < 2; mf++) {
            int row0 = rbase + warp_m * 32 + mf * 16 + qrow;
            if (row0 < NN)
                *(float2*)(out + (size_t)row0 * 128 + col) =
                    make_float2(acc[mf][nf][0] + b0, acc[mf][nf][1] + b1);
            int row1 = row0 + 8;
            if (row1 < NN)
                *(float2*)(out + (size_t)row1 * 128 + col) =
                    make_float2(acc[mf][nf][2] + b0, acc[mf][nf][3] + b1);
        }
    }
}

// ---------------- launch ------------------------------------------------------
extern "C" void kernel_launch(void* const* d_in, const int* in_sizes, int n_in,
                              void* d_out, int out_size) {
    const float* x        = (const float*)d_in[0];
    const int*   edge_src = (const int*)  d_in[1];
    const int*   edge_dst = (const int*)  d_in[2];
    const float* edge_val = (const float*)d_in[3];
    const float* W        = (const float*)d_in[4];
    const float* b        = (const float*)d_in[5];
    float* out = (float*)d_out;

    static bool attr_set = false;
    static void* degp = nullptr;
    if (!attr_set) {
        cudaFuncSetAttribute(gemm_mma_kernel,
                             cudaFuncAttributeMaxDynamicSharedMemorySize,
                             SMEM_GEMM_BYTES);
        cudaGetSymbolAddress(&degp, g_deg);
        attr_set = true;
    }

    uint2 *xhp, *f1p, *f2p;
    cudaGetSymbolAddress((void**)&xhp, g_xh);
    cudaGetSymbolAddress((void**)&f1p, g_f1);
    cudaGetSymbolAddress((void**)&f2p, g_f2);

    // 1) memset deg, then fused prep (x/W conversion + edge histogram)
    cudaMemsetAsync(degp, 0, NN * sizeof(int));
    prep_hist_kernel<<<XBLOCKS + WBLOCKS + HBLOCKS, 256>>>((const float4*)x, W,
                                                           edge_src);
    scan_local_kernel<<<NB, 1024>>>();
    scan_add_kernel<<<(NN + 255) / 256, 256>>>();
    scatter_kernel<<<(EE / 4 + 255) / 256, 256>>>(edge_src, edge_dst, edge_val);

    // 2) Two SpMM hops (fp16 gather, fp32 accumulate)
    int spmm_blocks = (NN + 7) / 8;
    spmm_kernel<<<spmm_blocks, 256>>>(xhp, f1p);
    spmm_kernel<<<spmm_blocks, 256>>>(f1p, f2p);

    // 3) Tensor-core dense layer, cp.async double-buffered
    gemm_mma_kernel<<<(NN + 127) / 128, 256, SMEM_GEMM_BYTES>>>(b, out);
}

// round 14
// speedup vs baseline: 1.4025x; 1.0858x over previous
#include <cuda_runtime.h>
#include <cuda_bf16.h>
#include <cuda_fp16.h>
#include <cstdint>

#define NN 100000
#define EE 1600000
#define D  128
#define KTOT 384
#define NB  ((NN + 1023) / 1024)            // 98 scan blocks
#define XBLOCKS ((NN * D / 8 + 255) / 256)  // 6250 xconv blocks
#define WBLOCKS ((128 * KTOT + 255) / 256)  // 192 wconv blocks
#define HBLOCKS ((EE / 4 + 255) / 256)      // 1563 hist blocks

typedef unsigned long long ull;

// ---------------- scratch (static device globals; no allocation) -------------
__device__ __align__(16) __half g_xh[(size_t)NN * D];   // fp16 image of x
__device__ __align__(16) __half g_f1[(size_t)NN * D];   // hop-1 (fp16)
__device__ __align__(16) __half g_f2[(size_t)NN * D];   // hop-2 (fp16)
__device__ int   g_deg[NN];
__device__ int   g_cursor[NN];
__device__ int   g_rowptr[NN + 1];
__device__ int   g_blocksum[NB];
__device__ int2  g_dstval[EE];          // packed (dst, val-bits)
// Pre-swizzled fp16 image of W: 6 K-chunks of [128 n][64 k] fp16 (16 KB each)
__device__ __align__(16) unsigned char g_Wh[6 * 16384];

// ---------------- PTX helpers -------------------------------------------------
__device__ __forceinline__ uint32_t smem_u32(const void* p) {
    uint32_t a;
    asm("{ .reg .u64 t; cvta.to.shared.u64 t, %1; cvt.u32.u64 %0, t; }" : "=r"(a) : "l"(p));
    return a;
}

#define LDSM4(R, A)                                                         \
    asm volatile("ldmatrix.sync.aligned.m8n8.x4.shared.b16 "                \
                 "{%0,%1,%2,%3}, [%4];"                                     \
                 : "=r"((R)[0]), "=r"((R)[1]), "=r"((R)[2]), "=r"((R)[3])   \
                 : "r"(A))

#define MMAF16(DD, AA, B0, B1)                                              \
    asm volatile("mma.sync.aligned.m16n8k16.row.col.f32.f16.f16.f32 "       \
                 "{%0,%1,%2,%3},{%4,%5,%6,%7},{%8,%9},{%0,%1,%2,%3};"       \
                 : "+f"((DD)[0]), "+f"((DD)[1]), "+f"((DD)[2]), "+f"((DD)[3]) \
                 : "r"((AA)[0]), "r"((AA)[1]), "r"((AA)[2]), "r"((AA)[3]),  \
                   "r"(B0), "r"(B1))

#define CP_ASYNC16(dst, src, sz)                                            \
    asm volatile("cp.async.ca.shared.global [%0], [%1], 16, %2;"            \
                 :: "r"(dst), "l"(src), "r"(sz))
#define CP_COMMIT() asm volatile("cp.async.commit_group;" ::: "memory")
#define CP_WAIT(n)  asm volatile("cp.async.wait_group %0;" :: "n"(n) : "memory")

__device__ __forceinline__ uint32_t swz(uint32_t bo) {
    return bo ^ ((bo >> 3) & 0x70);
}

__device__ __forceinline__ int warp_incl_scan(int val, int lane) {
    #pragma unroll
    for (int off = 1; off < 32; off <<= 1) {
        int t = __shfl_up_sync(0xffffffffu, val, off);
        if (lane >= off) val += t;
    }
    return val;
}

// ------ fused prep: x->fp16 | W->swizzled fp16 | edge-src histogram ----------
__global__ void prep_hist_kernel(const float4* __restrict__ x4,
                                 const float* __restrict__ W,
                                 const int* __restrict__ src) {
    if (blockIdx.x < XBLOCKS) {
        int i = blockIdx.x * 256 + threadIdx.x;      // over NN*D/8
        if (i >= NN * D / 8) return;
        float4 a = __ldg(&x4[i * 2]);
        float4 b = __ldg(&x4[i * 2 + 1]);
        __half2 h0 = __float22half2_rn(make_float2(a.x, a.y));
        __half2 h1 = __float22half2_rn(make_float2(a.z, a.w));
        __half2 h2 = __float22half2_rn(make_float2(b.x, b.y));
        __half2 h3 = __float22half2_rn(make_float2(b.z, b.w));
        uint4 o;
        o.x = *(uint32_t*)&h0; o.y = *(uint32_t*)&h1;
        o.z = *(uint32_t*)&h2; o.w = *(uint32_t*)&h3;
        ((uint4*)g_xh)[i] = o;
    } else if (blockIdx.x < XBLOCKS + WBLOCKS) {
        int i = (blockIdx.x - XBLOCKS) * 256 + threadIdx.x;   // over 128*384
        if (i >= 128 * KTOT) return;
        int n = i / KTOT, k = i % KTOT;
        __half h = __float2half_rn(W[i]);
        int c = k >> 6, kk = k & 63;
        uint32_t sw = swz((uint32_t)n * 128 + kk * 2);
        *(__half*)(g_Wh + c * 16384 + sw) = h;
    } else {
        int t = (blockIdx.x - XBLOCKS - WBLOCKS) * 256 + threadIdx.x;
        int e = t * 4;
        if (e + 3 < EE) {
            int4 s = __ldg((const int4*)(src + e));
            atomicAdd(&g_deg[s.x], 1);
            atomicAdd(&g_deg[s.y], 1);
            atomicAdd(&g_deg[s.z], 1);
            atomicAdd(&g_deg[s.w], 1);
        } else {
            for (int q = e; q < EE; q++) atomicAdd(&g_deg[__ldg(src + q)], 1);
        }
    }
}

// ---------------- CSR scan ----------------------------------------------------
__global__ __launch_bounds__(1024)
void scan_local_kernel() {
    __shared__ int warpsums[32];
    int tid = threadIdx.x, lane = tid & 31, wid = tid >> 5;
    int i = blockIdx.x * 1024 + tid;
    int v = (i < NN) ? g_deg[i] : 0;
    int val = warp_incl_scan(v, lane);
    if (lane == 31) warpsums[wid] = val;
    __syncthreads();
    if (wid == 0) warpsums[lane] = warp_incl_scan(warpsums[lane], lane);
    __syncthreads();
    int excl = val - v + (wid > 0 ? warpsums[wid - 1] : 0);
    if (i < NN) g_rowptr[i] = excl;
    if (tid == 0) g_blocksum[blockIdx.x] = warpsums[31];
}

__global__ __launch_bounds__(256)
void scan_add_kernel() {
    __shared__ int ws[4];
    __shared__ int boff[NB];
    int tid = threadIdx.x, lane = tid & 31, wid = tid >> 5;
    int v = 0, val = 0;
    if (tid < 128) {
        v = (tid < NB) ? g_blocksum[tid] : 0;
        val = warp_incl_scan(v, lane);
        if (lane == 31) ws[wid] = val;
    }
    __syncthreads();
    if (tid == 0) {
        int a = ws[0];
        ws[0] = 0;
        #pragma unroll
        for (int q = 1; q < 4; q++) { int t = ws[q]; ws[q] = a; a += t; }
    }
    __syncthreads();
    if (tid < NB) boff[tid] = val - v + ws[wid];
    __syncthreads();
    int i = blockIdx.x * 256 + tid;
    if (i < NN) {
        int r = g_rowptr[i] + boff[i >> 10];
        g_rowptr[i] = r;
        g_cursor[i] = r;
    }
    if (i == 0) g_rowptr[NN] = EE;
}

// x8 coarsened: eight outstanding position-atomics per thread
__global__ void scatter_kernel(const int* __restrict__ src,
                               const int* __restrict__ dst,
                               const float* __restrict__ val) {
    int t = blockIdx.x * blockDim.x + threadIdx.x;
    int e = t * 8;
    if (e + 7 < EE) {
        int4   s0 = __ldg((const int4*)(src + e));
        int4   s1 = __ldg((const int4*)(src + e + 4));
        int4   d0 = __ldg((const int4*)(dst + e));
        int4   d1 = __ldg((const int4*)(dst + e + 4));
        float4 v0 = __ldg((const float4*)(val + e));
        float4 v1 = __ldg((const float4*)(val + e + 4));
        int p0 = atomicAdd(&g_cursor[s0.x], 1);
        int p1 = atomicAdd(&g_cursor[s0.y], 1);
        int p2 = atomicAdd(&g_cursor[s0.z], 1);
        int p3 = atomicAdd(&g_cursor[s0.w], 1);
        int p4 = atomicAdd(&g_cursor[s1.x], 1);
        int p5 = atomicAdd(&g_cursor[s1.y], 1);
        int p6 = atomicAdd(&g_cursor[s1.z], 1);
        int p7 = atomicAdd(&g_cursor[s1.w], 1);
        g_dstval[p0] = make_int2(d0.x, __float_as_int(v0.x));
        g_dstval[p1] = make_int2(d0.y, __float_as_int(v0.y));
        g_dstval[p2] = make_int2(d0.z, __float_as_int(v0.z));
        g_dstval[p3] = make_int2(d0.w, __float_as_int(v0.w));
        g_dstval[p4] = make_int2(d1.x, __float_as_int(v1.x));
        g_dstval[p5] = make_int2(d1.y, __float_as_int(v1.y));
        g_dstval[p6] = make_int2(d1.z, __float_as_int(v1.z));
        g_dstval[p7] = make_int2(d1.w, __float_as_int(v1.w));
    } else {
        for (int q = e; q < EE; q++) {
            int dd = __ldg(dst + q);
            float vv = __ldg(val + q);
            int pos = atomicAdd(&g_cursor[__ldg(src + q)], 1);
            g_dstval[pos] = make_int2(dd, __float_as_int(vv));
        }
    }
}

// ---- SpMM (fp16 rows): HALF-warp per row, uint4 (16B) lanes, 8-deep unroll --
// 16 lanes x 16B = 256B row; 2 independent rows per warp -> 2x gather MLP.
__global__ __launch_bounds__(256)
void spmm_kernel(const uint4* __restrict__ fin, uint4* __restrict__ fout) {
    int hw   = (blockIdx.x * blockDim.x + threadIdx.x) >> 4;  // half-warp id
    int lane = threadIdx.x & 15;
    if (hw >= NN) return;
    int beg = __ldg(&g_rowptr[hw]);
    int end = __ldg(&g_rowptr[hw + 1]);

    float acc[8] = {0.f, 0.f, 0.f, 0.f, 0.f, 0.f, 0.f, 0.f};
    int j = beg;
    for (; j + 8 <= end; j += 8) {
        int2 m[8];
        uint4 a[8];
        #pragma unroll
        for (int q = 0; q < 8; q++) m[q] = __ldg(&g_dstval[j + q]);
        #pragma unroll
        for (int q = 0; q < 8; q++) a[q] = __ldg(&fin[(size_t)m[q].x * 16 + lane]);
        #pragma unroll
        for (int q = 0; q < 8; q++) {
            float v = __int_as_float(m[q].y);
            float2 f0 = __half22float2(*(__half2*)&a[q].x);
            float2 f1 = __half22float2(*(__half2*)&a[q].y);
            float2 f2 = __half22float2(*(__half2*)&a[q].z);
            float2 f3 = __half22float2(*(__half2*)&a[q].w);
            acc[0] = fmaf(v, f0.x, acc[0]);
            acc[1] = fmaf(v, f0.y, acc[1]);
            acc[2] = fmaf(v, f1.x, acc[2]);
            acc[3] = fmaf(v, f1.y, acc[3]);
            acc[4] = fmaf(v, f2.x, acc[4]);
            acc[5] = fmaf(v, f2.y, acc[5]);
            acc[6] = fmaf(v, f3.x, acc[6]);
            acc[7] = fmaf(v, f3.y, acc[7]);
        }
    }
    if (j + 4 <= end) {
        int2 m[4];
        uint4 a[4];
        #pragma unroll
        for (int q = 0; q < 4; q++) m[q] = __ldg(&g_dstval[j + q]);
        #pragma unroll
        for (int q = 0; q < 4; q++) a[q] = __ldg(&fin[(size_t)m[q].x * 16 + lane]);
        #pragma unroll
        for (int q = 0; q < 4; q++) {
            float v = __int_as_float(m[q].y);
            float2 f0 = __half22float2(*(__half2*)&a[q].x);
            float2 f1 = __half22float2(*(__half2*)&a[q].y);
            float2 f2 = __half22float2(*(__half2*)&a[q].z);
            float2 f3 = __half22float2(*(__half2*)&a[q].w);
            acc[0] = fmaf(v, f0.x, acc[0]);
            acc[1] = fmaf(v, f0.y, acc[1]);
            acc[2] = fmaf(v, f1.x, acc[2]);
            acc[3] = fmaf(v, f1.y, acc[3]);
            acc[4] = fmaf(v, f2.x, acc[4]);
            acc[5] = fmaf(v, f2.y, acc[5]);
            acc[6] = fmaf(v, f3.x, acc[6]);
            acc[7] = fmaf(v, f3.y, acc[7]);
        }
        j += 4;
    }
    for (; j < end; j++) {
        int2 m = __ldg(&g_dstval[j]);
        float v = __int_as_float(m.y);
        uint4 a = __ldg(&fin[(size_t)m.x * 16 + lane]);
        float2 f0 = __half22float2(*(__half2*)&a.x);
        float2 f1 = __half22float2(*(__half2*)&a.y);
        float2 f2 = __half22float2(*(__half2*)&a.z);
        float2 f3 = __half22float2(*(__half2*)&a.w);
        acc[0] = fmaf(v, f0.x, acc[0]);
        acc[1] = fmaf(v, f0.y, acc[1]);
        acc[2] = fmaf(v, f1.x, acc[2]);
        acc[3] = fmaf(v, f1.y, acc[3]);
        acc[4] = fmaf(v, f2.x, acc[4]);
        acc[5] = fmaf(v, f2.y, acc[5]);
        acc[6] = fmaf(v, f3.x, acc[6]);
        acc[7] = fmaf(v, f3.y, acc[7]);
    }
    __half2 o0 = __float22half2_rn(make_float2(acc[0], acc[1]));
    __half2 o1 = __float22half2_rn(make_float2(acc[2], acc[3]));
    __half2 o2 = __float22half2_rn(make_float2(acc[4], acc[5]));
    __half2 o3 = __float22half2_rn(make_float2(acc[6], acc[7]));
    uint4 o;
    o.x = *(uint32_t*)&o0; o.y = *(uint32_t*)&o1;
    o.z = *(uint32_t*)&o2; o.w = *(uint32_t*)&o3;
    fout[(size_t)hw * 16 + lane] = o;
}

// ---------------- mma.sync GEMM, cp.async double-buffered ---------------------
#define STAGE_BYTES 32768
#define SMEM_GEMM_BYTES (1024 + 2 * STAGE_BYTES)

__global__ __launch_bounds__(256, 2)
void gemm_mma_kernel(const float* __restrict__ bias,
                     float* __restrict__ out) {
    extern __shared__ unsigned char dsm[];
    const int tid  = threadIdx.x;
    const int lane = tid & 31;
    const int wid  = tid >> 5;
    const int warp_m = wid & 3;
    const int warp_n = wid >> 2;
    const int rbase  = blockIdx.x * 128;

    uint32_t sb0  = smem_u32(dsm);
    uint32_t base = (sb0 + 1023) & ~1023u;

    auto issue_chunk = [&](int c, int buf) {
        const uint4* fsrc = (const uint4*)((c < 2) ? g_xh : (c < 4) ? g_f1 : g_f2);
        int koff = (c & 1) * 8;                       // uint4 (16B) offset in row
        uint32_t abase = base + buf * STAGE_BYTES;
        #pragma unroll
        for (int it = 0; it < 4; it++) {
            int idx = tid + it * 256;                 // 1024 x 16B
            int row = idx >> 3, c8 = idx & 7;
            int grow = rbase + row;
            const uint4* src = fsrc + ((grow < NN) ? ((size_t)grow * 16 + koff + c8) : 0);
            CP_ASYNC16(abase + swz((uint32_t)row * 128 + c8 * 16), src,
                       (grow < NN) ? 16 : 0);
        }
        const uint4* wh = (const uint4*)(g_Wh + c * 16384);
        uint32_t bbase = abase + 16384;
        #pragma unroll
        for (int it = 0; it < 4; it++) {
            int i = tid + it * 256;
            CP_ASYNC16(bbase + i * 16, wh + i, 16);
        }
    };

    float acc[2][8][4];
    #pragma unroll
    for (int mf = 0; mf < 2; mf++)
        #pragma unroll
        for (int nf = 0; nf < 8; nf++)
            #pragma unroll
            for (int q = 0; q < 4; q++) acc[mf][nf][q] = 0.f;

    const int g = lane >> 3, r = lane & 7;
    const int a_row_off = r + (g & 1) * 8;
    const int a_k_off   = (g >> 1) * 8;
    const int b_n_off   = r + (g >> 1) * 8;
    const int b_k_off   = (g & 1) * 8;

    issue_chunk(0, 0);
    CP_COMMIT();

    #pragma unroll
    for (int c = 0; c < 6; c++) {
        if (c < 5) {
            issue_chunk(c + 1, (c + 1) & 1);
            CP_COMMIT();
            CP_WAIT(1);
        } else {
            CP_WAIT(0);
        }
        __syncthreads();
        const uint32_t At = base + (c & 1) * STAGE_BYTES;
        const uint32_t Bh = At + 16384;
        #pragma unroll
        for (int ks = 0; ks < 4; ks++) {
            const int k0 = ks * 16;
            uint32_t ah[2][4];
            #pragma unroll
            for (int mf = 0; mf < 2; mf++) {
                uint32_t sw = swz((uint32_t)(warp_m * 32 + mf * 16 + a_row_off) * 128
                                  + (k0 + a_k_off) * 2);
                LDSM4(ah[mf], At + sw);
            }
            #pragma unroll
            for (int bq = 0; bq < 4; bq++) {
                uint32_t sw = swz((uint32_t)(warp_n * 64 + bq * 16 + b_n_off) * 128
                                  + (k0 + b_k_off) * 2);
                uint32_t bh[4];
                LDSM4(bh, Bh + sw);
                #pragma unroll
                for (int mf = 0; mf < 2; mf++) {
                    MMAF16(acc[mf][bq * 2 + 0], ah[mf], bh[0], bh[1]);
                    MMAF16(acc[mf][bq * 2 + 1], ah[mf], bh[2], bh[3]);
                }
            }
        }
        __syncthreads();
    }

    // ---- epilogue: bias + store ----
    const int qrow = lane >> 2, qcol = (lane & 3) * 2;
    #pragma unroll
    for (int nf = 0; nf < 8; nf++) {
        int col = warp_n * 64 + nf * 8 + qcol;
        float b0 = __ldg(&bias[col]);
        float b1 = __ldg(&bias[col + 1]);
        #pragma unroll
        for (int mf = 0; mf < 2; mf++) {
            int row0 = rbase + warp_m * 32 + mf * 16 + qrow;
            if (row0 < NN)
                *(float2*)(out + (size_t)row0 * 128 + col) =
                    make_float2(acc[mf][nf][0] + b0, acc[mf][nf][1] + b1);
            int row1 = row0 + 8;
            if (row1 < NN)
                *(float2*)(out + (size_t)row1 * 128 + col) =
                    make_float2(acc[mf][nf][2] + b0, acc[mf][nf][3] + b1);
        }
    }
}

// ---------------- launch ------------------------------------------------------
extern "C" void kernel_launch(void* const* d_in, const int* in_sizes, int n_in,
                              void* d_out, int out_size) {
    const float* x        = (const float*)d_in[0];
    const int*   edge_src = (const int*)  d_in[1];
    const int*   edge_dst = (const int*)  d_in[2];
    const float* edge_val = (const float*)d_in[3];
    const float* W        = (const float*)d_in[4];
    const float* b        = (const float*)d_in[5];
    float* out = (float*)d_out;

    static bool attr_set = false;
    static void* degp = nullptr;
    if (!attr_set) {
        cudaFuncSetAttribute(gemm_mma_kernel,
                             cudaFuncAttributeMaxDynamicSharedMemorySize,
                             SMEM_GEMM_BYTES);
        cudaGetSymbolAddress(&degp, g_deg);
        attr_set = true;
    }

    uint4 *xhp, *f1p, *f2p;
    cudaGetSymbolAddress((void**)&xhp, g_xh);
    cudaGetSymbolAddress((void**)&f1p, g_f1);
    cudaGetSymbolAddress((void**)&f2p, g_f2);

    // 1) memset deg, fused prep (x/W conversion + edge histogram), scan, scatter
    cudaMemsetAsync(degp, 0, NN * sizeof(int));
    prep_hist_kernel<<<XBLOCKS + WBLOCKS + HBLOCKS, 256>>>((const float4*)x, W,
                                                           edge_src);
    scan_local_kernel<<<NB, 1024>>>();
    scan_add_kernel<<<(NN + 255) / 256, 256>>>();
    scatter_kernel<<<(EE / 8 + 255) / 256, 256>>>(edge_src, edge_dst, edge_val);

    // 2) Two SpMM hops (fp16 gather, fp32 accumulate) — half-warp per row
    int spmm_blocks = (NN + 15) / 16;
    spmm_kernel<<<spmm_blocks, 256>>>(xhp, f1p);
    spmm_kernel<<<spmm_blocks, 256>>>(f1p, f2p);

    // 3) Tensor-core dense layer, cp.async double-buffered
    gemm_mma_kernel<<<(NN + 127) / 128, 256, SMEM_GEMM_BYTES>>>(b, out);
}

// round 15
// speedup vs baseline: 1.4324x; 1.0213x over previous
#include <cuda_runtime.h>
#include <cuda_bf16.h>
#include <cuda_fp16.h>
#include <cstdint>

#define NN 100000
#define EE 1600000
#define D  128
#define KTOT 384
#define NB  ((NN + 1023) / 1024)            // 98 scan blocks
#define XBLOCKS ((NN * D / 8 + 255) / 256)  // 6250 xconv blocks
#define WBLOCKS ((128 * KTOT + 255) / 256)  // 192 wconv blocks
#define HBLOCKS ((EE / 4 + 255) / 256)      // 1563 hist blocks

typedef unsigned long long ull;

// ---------------- scratch (static device globals; no allocation) -------------
__device__ __align__(16) __half g_xh[(size_t)NN * D];   // fp16 image of x
__device__ __align__(16) __half g_f1[(size_t)NN * D];   // hop-1 (fp16)
__device__ __align__(16) __half g_f2[(size_t)NN * D];   // hop-2 (fp16)
__device__ int   g_deg[NN];
__device__ int   g_rowptr[NN + 1];
__device__ int   g_blocksum[NB];
__device__ int   g_rank[EE];            // per-edge arrival rank within src node
__device__ int2  g_dstval[EE];          // packed (dst, val-bits)
// Pre-swizzled fp16 image of W: 6 K-chunks of [128 n][64 k] fp16 (16 KB each)
__device__ __align__(16) unsigned char g_Wh[6 * 16384];

// ---------------- PTX helpers -------------------------------------------------
__device__ __forceinline__ uint32_t smem_u32(const void* p) {
    uint32_t a;
    asm("{ .reg .u64 t; cvta.to.shared.u64 t, %1; cvt.u32.u64 %0, t; }" : "=r"(a) : "l"(p));
    return a;
}

#define LDSM4(R, A)                                                         \
    asm volatile("ldmatrix.sync.aligned.m8n8.x4.shared.b16 "                \
                 "{%0,%1,%2,%3}, [%4];"                                     \
                 : "=r"((R)[0]), "=r"((R)[1]), "=r"((R)[2]), "=r"((R)[3])   \
                 : "r"(A))

#define MMAF16(DD, AA, B0, B1)                                              \
    asm volatile("mma.sync.aligned.m16n8k16.row.col.f32.f16.f16.f32 "       \
                 "{%0,%1,%2,%3},{%4,%5,%6,%7},{%8,%9},{%0,%1,%2,%3};"       \
                 : "+f"((DD)[0]), "+f"((DD)[1]), "+f"((DD)[2]), "+f"((DD)[3]) \
                 : "r"((AA)[0]), "r"((AA)[1]), "r"((AA)[2]), "r"((AA)[3]),  \
                   "r"(B0), "r"(B1))

#define CP_ASYNC16(dst, src, sz)                                            \
    asm volatile("cp.async.ca.shared.global [%0], [%1], 16, %2;"            \
                 :: "r"(dst), "l"(src), "r"(sz))
#define CP_COMMIT() asm volatile("cp.async.commit_group;" ::: "memory")
#define CP_WAIT(n)  asm volatile("cp.async.wait_group %0;" :: "n"(n) : "memory")

__device__ __forceinline__ uint32_t swz(uint32_t bo) {
    return bo ^ ((bo >> 3) & 0x70);
}

__device__ __forceinline__ int warp_incl_scan(int val, int lane) {
    #pragma unroll
    for (int off = 1; off < 32; off <<= 1) {
        int t = __shfl_up_sync(0xffffffffu, val, off);
        if (lane >= off) val += t;
    }
    return val;
}

// ------ fused prep: x->fp16 | W->swizzled fp16 | edge histogram + rank -------
__global__ void prep_hist_kernel(const float4* __restrict__ x4,
                                 const float* __restrict__ W,
                                 const int* __restrict__ src) {
    if (blockIdx.x < XBLOCKS) {
        int i = blockIdx.x * 256 + threadIdx.x;      // over NN*D/8
        if (i >= NN * D / 8) return;
        float4 a = __ldg(&x4[i * 2]);
        float4 b = __ldg(&x4[i * 2 + 1]);
        __half2 h0 = __float22half2_rn(make_float2(a.x, a.y));
        __half2 h1 = __float22half2_rn(make_float2(a.z, a.w));
        __half2 h2 = __float22half2_rn(make_float2(b.x, b.y));
        __half2 h3 = __float22half2_rn(make_float2(b.z, b.w));
        uint4 o;
        o.x = *(uint32_t*)&h0; o.y = *(uint32_t*)&h1;
        o.z = *(uint32_t*)&h2; o.w = *(uint32_t*)&h3;
        ((uint4*)g_xh)[i] = o;
    } else if (blockIdx.x < XBLOCKS + WBLOCKS) {
        int i = (blockIdx.x - XBLOCKS) * 256 + threadIdx.x;   // over 128*384
        if (i >= 128 * KTOT) return;
        int n = i / KTOT, k = i % KTOT;
        __half h = __float2half_rn(W[i]);
        int c = k >> 6, kk = k & 63;
        uint32_t sw = swz((uint32_t)n * 128 + kk * 2);
        *(__half*)(g_Wh + c * 16384 + sw) = h;
    } else {
        int t = (blockIdx.x - XBLOCKS - WBLOCKS) * 256 + threadIdx.x;
        int e = t * 4;
        if (e + 3 < EE) {
            int4 s = __ldg((const int4*)(src + e));
            int4 r;
            r.x = atomicAdd(&g_deg[s.x], 1);
            r.y = atomicAdd(&g_deg[s.y], 1);
            r.z = atomicAdd(&g_deg[s.z], 1);
            r.w = atomicAdd(&g_deg[s.w], 1);
            *(int4*)(g_rank + e) = r;
        } else {
            for (int q = e; q < EE; q++)
                g_rank[q] = atomicAdd(&g_deg[__ldg(src + q)], 1);
        }
    }
}

// ---------------- CSR scan ----------------------------------------------------
__global__ __launch_bounds__(1024)
void scan_local_kernel() {
    __shared__ int warpsums[32];
    int tid = threadIdx.x, lane = tid & 31, wid = tid >> 5;
    int i = blockIdx.x * 1024 + tid;
    int v = (i < NN) ? g_deg[i] : 0;
    int val = warp_incl_scan(v, lane);
    if (lane == 31) warpsums[wid] = val;
    __syncthreads();
    if (wid == 0) warpsums[lane] = warp_incl_scan(warpsums[lane], lane);
    __syncthreads();
    int excl = val - v + (wid > 0 ? warpsums[wid - 1] : 0);
    if (i < NN) g_rowptr[i] = excl;
    if (tid == 0) g_blocksum[blockIdx.x] = warpsums[31];
}

__global__ __launch_bounds__(256)
void scan_add_kernel() {
    __shared__ int ws[4];
    __shared__ int boff[NB];
    int tid = threadIdx.x, lane = tid & 31, wid = tid >> 5;
    int v = 0, val = 0;
    if (tid < 128) {
        v = (tid < NB) ? g_blocksum[tid] : 0;
        val = warp_incl_scan(v, lane);
        if (lane == 31) ws[wid] = val;
    }
    __syncthreads();
    if (tid == 0) {
        int a = ws[0];
        ws[0] = 0;
        #pragma unroll
        for (int q = 1; q < 4; q++) { int t = ws[q]; ws[q] = a; a += t; }
    }
    __syncthreads();
    if (tid < NB) boff[tid] = val - v + ws[wid];
    __syncthreads();
    int i = blockIdx.x * 256 + tid;
    if (i < NN) g_rowptr[i] += boff[i >> 10];
    if (i == 0) g_rowptr[NN] = EE;
}

// Atomic-free scatter: position = rowptr[src] + rank (rank saved during hist)
__global__ void scatter_kernel(const int* __restrict__ src,
                               const int* __restrict__ dst,
                               const float* __restrict__ val) {
    int t = blockIdx.x * blockDim.x + threadIdx.x;
    int e = t * 4;
    if (e + 3 < EE) {
        int4   s = __ldg((const int4*)(src + e));
        int4   r = *(const int4*)(g_rank + e);
        int4   d = __ldg((const int4*)(dst + e));
        float4 v = __ldg((const float4*)(val + e));
        g_dstval[__ldg(&g_rowptr[s.x]) + r.x] = make_int2(d.x, __float_as_int(v.x));
        g_dstval[__ldg(&g_rowptr[s.y]) + r.y] = make_int2(d.y, __float_as_int(v.y));
        g_dstval[__ldg(&g_rowptr[s.z]) + r.z] = make_int2(d.z, __float_as_int(v.z));
        g_dstval[__ldg(&g_rowptr[s.w]) + r.w] = make_int2(d.w, __float_as_int(v.w));
    } else {
        for (int q = e; q < EE; q++) {
            int ss = __ldg(src + q);
            g_dstval[__ldg(&g_rowptr[ss]) + g_rank[q]] =
                make_int2(__ldg(dst + q), __float_as_int(__ldg(val + q)));
        }
    }
}

// ---- SpMM (fp16 rows): HALF-warp per row, uint4 (16B) lanes, 8-deep unroll --
__global__ __launch_bounds__(256)
void spmm_kernel(const uint4* __restrict__ fin, uint4* __restrict__ fout) {
    int hw   = (blockIdx.x * blockDim.x + threadIdx.x) >> 4;  // half-warp id
    int lane = threadIdx.x & 15;
    if (hw >= NN) return;
    int beg = __ldg(&g_rowptr[hw]);
    int end = __ldg(&g_rowptr[hw + 1]);

    float acc[8] = {0.f, 0.f, 0.f, 0.f, 0.f, 0.f, 0.f, 0.f};
    int j = beg;
    for (; j + 8 <= end; j += 8) {
        int2 m[8];
        uint4 a[8];
        #pragma unroll
        for (int q = 0; q < 8; q++) m[q] = __ldg(&g_dstval[j + q]);
        #pragma unroll
        for (int q = 0; q < 8; q++) a[q] = __ldg(&fin[(size_t)m[q].x * 16 + lane]);
        #pragma unroll
        for (int q = 0; q < 8; q++) {
            float v = __int_as_float(m[q].y);
            float2 f0 = __half22float2(*(__half2*)&a[q].x);
            float2 f1 = __half22float2(*(__half2*)&a[q].y);
            float2 f2 = __half22float2(*(__half2*)&a[q].z);
            float2 f3 = __half22float2(*(__half2*)&a[q].w);
            acc[0] = fmaf(v, f0.x, acc[0]);
            acc[1] = fmaf(v, f0.y, acc[1]);
            acc[2] = fmaf(v, f1.x, acc[2]);
            acc[3] = fmaf(v, f1.y, acc[3]);
            acc[4] = fmaf(v, f2.x, acc[4]);
            acc[5] = fmaf(v, f2.y, acc[5]);
            acc[6] = fmaf(v, f3.x, acc[6]);
            acc[7] = fmaf(v, f3.y, acc[7]);
        }
    }
    if (j + 4 <= end) {
        int2 m[4];
        uint4 a[4];
        #pragma unroll
        for (int q = 0; q < 4; q++) m[q] = __ldg(&g_dstval[j + q]);
        #pragma unroll
        for (int q = 0; q < 4; q++) a[q] = __ldg(&fin[(size_t)m[q].x * 16 + lane]);
        #pragma unroll
        for (int q = 0; q < 4; q++) {
            float v = __int_as_float(m[q].y);
            float2 f0 = __half22float2(*(__half2*)&a[q].x);
            float2 f1 = __half22float2(*(__half2*)&a[q].y);
            float2 f2 = __half22float2(*(__half2*)&a[q].z);
            float2 f3 = __half22float2(*(__half2*)&a[q].w);
            acc[0] = fmaf(v, f0.x, acc[0]);
            acc[1] = fmaf(v, f0.y, acc[1]);
            acc[2] = fmaf(v, f1.x, acc[2]);
            acc[3] = fmaf(v, f1.y, acc[3]);
            acc[4] = fmaf(v, f2.x, acc[4]);
            acc[5] = fmaf(v, f2.y, acc[5]);
            acc[6] = fmaf(v, f3.x, acc[6]);
            acc[7] = fmaf(v, f3.y, acc[7]);
        }
        j += 4;
    }
    for (; j < end; j++) {
        int2 m = __ldg(&g_dstval[j]);
        float v = __int_as_float(m.y);
        uint4 a = __ldg(&fin[(size_t)m.x * 16 + lane]);
        float2 f0 = __half22float2(*(__half2*)&a.x);
        float2 f1 = __half22float2(*(__half2*)&a.y);
        float2 f2 = __half22float2(*(__half2*)&a.z);
        float2 f3 = __half22float2(*(__half2*)&a.w);
        acc[0] = fmaf(v, f0.x, acc[0]);
        acc[1] = fmaf(v, f0.y, acc[1]);
        acc[2] = fmaf(v, f1.x, acc[2]);
        acc[3] = fmaf(v, f1.y, acc[3]);
        acc[4] = fmaf(v, f2.x, acc[4]);
        acc[5] = fmaf(v, f2.y, acc[5]);
        acc[6] = fmaf(v, f3.x, acc[6]);
        acc[7] = fmaf(v, f3.y, acc[7]);
    }
    __half2 o0 = __float22half2_rn(make_float2(acc[0], acc[1]));
    __half2 o1 = __float22half2_rn(make_float2(acc[2], acc[3]));
    __half2 o2 = __float22half2_rn(make_float2(acc[4], acc[5]));
    __half2 o3 = __float22half2_rn(make_float2(acc[6], acc[7]));
    uint4 o;
    o.x = *(uint32_t*)&o0; o.y = *(uint32_t*)&o1;
    o.z = *(uint32_t*)&o2; o.w = *(uint32_t*)&o3;
    fout[(size_t)hw * 16 + lane] = o;
}

// ---------------- mma.sync GEMM, cp.async double-buffered ---------------------
#define STAGE_BYTES 32768
#define SMEM_GEMM_BYTES (1024 + 2 * STAGE_BYTES)

__global__ __launch_bounds__(256, 2)
void gemm_mma_kernel(const float* __restrict__ bias,
                     float* __restrict__ out) {
    extern __shared__ unsigned char dsm[];
    const int tid  = threadIdx.x;
    const int lane = tid & 31;
    const int wid  = tid >> 5;
    const int warp_m = wid & 3;
    const int warp_n = wid >> 2;
    const int rbase  = blockIdx.x * 128;

    uint32_t sb0  = smem_u32(dsm);
    uint32_t base = (sb0 + 1023) & ~1023u;

    auto issue_chunk = [&](int c, int buf) {
        const uint4* fsrc = (const uint4*)((c < 2) ? g_xh : (c < 4) ? g_f1 : g_f2);
        int koff = (c & 1) * 8;                       // uint4 (16B) offset in row
        uint32_t abase = base + buf * STAGE_BYTES;
        #pragma unroll
        for (int it = 0; it < 4; it++) {
            int idx = tid + it * 256;                 // 1024 x 16B
            int row = idx >> 3, c8 = idx & 7;
            int grow = rbase + row;
            const uint4* src = fsrc + ((grow < NN) ? ((size_t)grow * 16 + koff + c8) : 0);
            CP_ASYNC16(abase + swz((uint32_t)row * 128 + c8 * 16), src,
                       (grow < NN) ? 16 : 0);
        }
        const uint4* wh = (const uint4*)(g_Wh + c * 16384);
        uint32_t bbase = abase + 16384;
        #pragma unroll
        for (int it = 0; it < 4; it++) {
            int i = tid + it * 256;
            CP_ASYNC16(bbase + i * 16, wh + i, 16);
        }
    };

    float acc[2][8][4];
    #pragma unroll
    for (int mf = 0; mf < 2; mf++)
        #pragma unroll
        for (int nf = 0; nf < 8; nf++)
            #pragma unroll
            for (int q = 0; q < 4; q++) acc[mf][nf][q] = 0.f;

    const int g = lane >> 3, r = lane & 7;
    const int a_row_off = r + (g & 1) * 8;
    const int a_k_off   = (g >> 1) * 8;
    const int b_n_off   = r + (g >> 1) * 8;
    const int b_k_off   = (g & 1) * 8;

    issue_chunk(0, 0);
    CP_COMMIT();

    #pragma unroll
    for (int c = 0; c < 6; c++) {
        if (c < 5) {
            issue_chunk(c + 1, (c + 1) & 1);
            CP_COMMIT();
            CP_WAIT(1);
        } else {
            CP_WAIT(0);
        }
        __syncthreads();
        const uint32_t At = base + (c & 1) * STAGE_BYTES;
        const uint32_t Bh = At + 16384;
        #pragma unroll
        for (int ks = 0; ks < 4; ks++) {
            const int k0 = ks * 16;
            uint32_t ah[2][4];
            #pragma unroll
            for (int mf = 0; mf < 2; mf++) {
                uint32_t sw = swz((uint32_t)(warp_m * 32 + mf * 16 + a_row_off) * 128
                                  + (k0 + a_k_off) * 2);
                LDSM4(ah[mf], At + sw);
            }
            #pragma unroll
            for (int bq = 0; bq < 4; bq++) {
                uint32_t sw = swz((uint32_t)(warp_n * 64 + bq * 16 + b_n_off) * 128
                                  + (k0 + b_k_off) * 2);
                uint32_t bh[4];
                LDSM4(bh, Bh + sw);
                #pragma unroll
                for (int mf = 0; mf < 2; mf++) {
                    MMAF16(acc[mf][bq * 2 + 0], ah[mf], bh[0], bh[1]);
                    MMAF16(acc[mf][bq * 2 + 1], ah[mf], bh[2], bh[3]);
                }
            }
        }
        __syncthreads();
    }

    // ---- epilogue: bias + store ----
    const int qrow = lane >> 2, qcol = (lane & 3) * 2;
    #pragma unroll
    for (int nf = 0; nf < 8; nf++) {
        int col = warp_n * 64 + nf * 8 + qcol;
        float b0 = __ldg(&bias[col]);
        float b1 = __ldg(&bias[col + 1]);
        #pragma unroll
        for (int mf = 0; mf < 2; mf++) {
            int row0 = rbase + warp_m * 32 + mf * 16 + qrow;
            if (row0 < NN)
                *(float2*)(out + (size_t)row0 * 128 + col) =
                    make_float2(acc[mf][nf][0] + b0, acc[mf][nf][1] + b1);
            int row1 = row0 + 8;
            if (row1 < NN)
                *(float2*)(out + (size_t)row1 * 128 + col) =
                    make_float2(acc[mf][nf][2] + b0, acc[mf][nf][3] + b1);
        }
    }
}

// ---------------- launch ------------------------------------------------------
extern "C" void kernel_launch(void* const* d_in, const int* in_sizes, int n_in,
                              void* d_out, int out_size) {
    const float* x        = (const float*)d_in[0];
    const int*   edge_src = (const int*)  d_in[1];
    const int*   edge_dst = (const int*)  d_in[2];
    const float* edge_val = (const float*)d_in[3];
    const float* W        = (const float*)d_in[4];
    const float* b        = (const float*)d_in[5];
    float* out = (float*)d_out;

    static bool attr_set = false;
    static void* degp = nullptr;
    if (!attr_set) {
        cudaFuncSetAttribute(gemm_mma_kernel,
                             cudaFuncAttributeMaxDynamicSharedMemorySize,
                             SMEM_GEMM_BYTES);
        cudaGetSymbolAddress(&degp, g_deg);
        attr_set = true;
    }

    uint4 *xhp, *f1p, *f2p;
    cudaGetSymbolAddress((void**)&xhp, g_xh);
    cudaGetSymbolAddress((void**)&f1p, g_f1);
    cudaGetSymbolAddress((void**)&f2p, g_f2);

    // 1) memset deg, fused prep (conversions + histogram/rank), scan, scatter
    cudaMemsetAsync(degp, 0, NN * sizeof(int));
    prep_hist_kernel<<<XBLOCKS + WBLOCKS + HBLOCKS, 256>>>((const float4*)x, W,
                                                           edge_src);
    scan_local_kernel<<<NB, 1024>>>();
    scan_add_kernel<<<(NN + 255) / 256, 256>>>();
    scatter_kernel<<<(EE / 4 + 255) / 256, 256>>>(edge_src, edge_dst, edge_val);

    // 2) Two SpMM hops (fp16 gather, fp32 accumulate) — half-warp per row
    int spmm_blocks = (NN + 15) / 16;
    spmm_kernel<<<spmm_blocks, 256>>>(xhp, f1p);
    spmm_kernel<<<spmm_blocks, 256>>>(f1p, f2p);

    // 3) Tensor-core dense layer, cp.async double-buffered
    gemm_mma_kernel<<<(NN + 127) / 128, 256, SMEM_GEMM_BYTES>>>(b, out);
}